// round 2
// baseline (speedup 1.0000x reference)
#include <cuda_runtime.h>
#include <cstdint>
#include <cstddef>

// Problem constants (from reference: T,H,I,E = 8192,1024,2816,8)
#define T_TOK 8192
#define H_DIM 1024
#define I_DIM 2816
#define N_EXP 8

// GEMM tiling
#define BM 128
#define BN 64
#define BK 16

#define MAX_TILES ((T_TOK / BM) + N_EXP)   // 72 : sum ceil(cnt_e/BM) <= T/BM + E
#define PADDED    (MAX_TILES * BM)         // 9216

// ---------------------------------------------------------------------------
// Device scratch (allocations are forbidden; __device__ globals are the
// sanctioned scratch mechanism). Everything is fully rewritten every launch.
// ---------------------------------------------------------------------------
__device__ int   g_counts[N_EXP];
__device__ int   g_wpos[N_EXP];
__device__ int   g_tile_expert[MAX_TILES];
__device__ int   g_perm[PADDED];                      // padded slots = -1
__device__ float g_X[(size_t)PADDED * H_DIM];         // gathered tokens (grouped)
__device__ float g_Hid[(size_t)PADDED * I_DIM];       // silu(gate)*up

// ---------------------------------------------------------------------------
// Packed f32x2 helpers (FFMA2: 2x fp32 FMA throughput vs 3-reg FFMA on sm_10x)
// ---------------------------------------------------------------------------
__device__ __forceinline__ unsigned long long f2pk(float x, float y) {
    unsigned long long r;
    asm("mov.b64 %0, {%1, %2};" : "=l"(r) : "f"(x), "f"(y));
    return r;
}
__device__ __forceinline__ float2 f2un(unsigned long long v) {
    float2 r;
    asm("mov.b64 {%0, %1}, %2;" : "=f"(r.x), "=f"(r.y) : "l"(v));
    return r;
}
__device__ __forceinline__ void ffma2(unsigned long long& d,
                                      unsigned long long a,
                                      unsigned long long b) {
    asm("fma.rn.f32x2 %0, %1, %2, %0;" : "+l"(d) : "l"(a), "l"(b));
}

__device__ __forceinline__ float silu_f(float v) {
    // x * sigmoid(x); __expf rel err ~2^-22, far inside 1e-3 tolerance
    return v / (1.0f + __expf(-v));
}

// ---------------------------------------------------------------------------
// Permutation build: init -> count -> scan(+tile map) -> scatter -> gather
// ---------------------------------------------------------------------------
__global__ void k_init() {
    int i = blockIdx.x * blockDim.x + threadIdx.x;
    if (i < PADDED) g_perm[i] = -1;
    if (i < N_EXP)  g_counts[i] = 0;
}

__global__ void k_count(const int* __restrict__ idx) {
    int t = blockIdx.x * blockDim.x + threadIdx.x;
    if (t < T_TOK) atomicAdd(&g_counts[idx[t]], 1);
}

__global__ void k_scan() {
    if (threadIdx.x == 0 && blockIdx.x == 0) {
        int base = 0, tile = 0;
        for (int e = 0; e < N_EXP; ++e) {
            g_wpos[e] = base;                       // segment start (= scatter cursor)
            int nt = (g_counts[e] + BM - 1) / BM;   // tiles for this expert
            for (int i = 0; i < nt; ++i) g_tile_expert[tile++] = e;
            base += nt * BM;                        // pad segment to BM
        }
        for (; tile < MAX_TILES; ++tile) g_tile_expert[tile] = 0; // dead tiles
    }
}

__global__ void k_scatter(const int* __restrict__ idx) {
    int t = blockIdx.x * blockDim.x + threadIdx.x;
    if (t < T_TOK) {
        int p = atomicAdd(&g_wpos[idx[t]], 1);      // order within expert arbitrary
        g_perm[p] = t;                              // (output is order-independent)
    }
}

__global__ void k_gather(const float* __restrict__ x) {
    int row = blockIdx.x;                           // one padded row per block
    int t = g_perm[row];
    float4* dst = reinterpret_cast<float4*>(g_X + (size_t)row * H_DIM);
    int j = threadIdx.x;                            // H_DIM/4 == 256 == blockDim
    if (t >= 0) {
        const float4* src = reinterpret_cast<const float4*>(x + (size_t)t * H_DIM);
        dst[j] = src[j];
    } else {
        dst[j] = make_float4(0.f, 0.f, 0.f, 0.f);   // padding rows -> zero
    }
}

// ---------------------------------------------------------------------------
// Grouped GEMM core. A and B are both K-major (row-major with K contiguous):
//   C[m,n] = sum_k A[m,k] * W[e, n, k]
// FUSED=true : A = g_X   (K=H),  N=I, two weight operands (Wg, Wu),
//              epilogue writes g_Hid = silu(gate) * up.
// FUSED=false: A = g_Hid (K=I),  N=H, one weight operand (Wd),
//              epilogue scatters rows to d_out via g_perm.
// 256 threads, each computes 8(M) x 4(N) outputs; double-buffered SMEM.
// ---------------------------------------------------------------------------
template <bool FUSED, int K, int NTOT>
__global__ __launch_bounds__(256, 2) void k_gemm(const float* __restrict__ W0,
                                                 const float* __restrict__ W1,
                                                 float* __restrict__ Out) {
    __shared__ float As [2][BK][BM + 4];
    __shared__ float B0s[2][BK][BN + 4];
    __shared__ float B1s[2][BK][BN + 4];

    const float* __restrict__ A = FUSED ? g_X : g_Hid;

    const int tid = threadIdx.x;
    const int tx  = tid & 15;       // N direction (4 cols each)
    const int ty  = tid >> 4;       // M direction (8 rows each)
    const int mt  = blockIdx.y;
    const int nt  = blockIdx.x;
    const int expert = g_tile_expert[mt];
    const int mBase  = mt * BM;
    const int nBase  = nt * BN;

    const int lrow = tid >> 2;          // 0..63 (load row)
    const int lk   = (tid & 3) << 2;    // 0,4,8,12 (load k within BK)

    const float* Ap  = A  + (size_t)(mBase + lrow) * K + lk;
    const float* W0p = W0 + ((size_t)expert * NTOT + nBase + lrow) * K + lk;
    const float* W1p = FUSED ? (W1 + ((size_t)expert * NTOT + nBase + lrow) * K + lk)
                             : W0p;

    float4 ra0, ra1, rb0, rb1;

#define LDG_TILE(kt_)                                                        \
    do {                                                                     \
        const float* ap_ = Ap + (size_t)(kt_) * BK;                          \
        ra0 = *reinterpret_cast<const float4*>(ap_);                         \
        ra1 = *reinterpret_cast<const float4*>(ap_ + (size_t)64 * K);        \
        rb0 = *reinterpret_cast<const float4*>(W0p + (size_t)(kt_) * BK);    \
        if (FUSED)                                                           \
            rb1 = *reinterpret_cast<const float4*>(W1p + (size_t)(kt_) * BK);\
    } while (0)

#define STS_TILE(buf_)                                                       \
    do {                                                                     \
        As[buf_][lk + 0][lrow]      = ra0.x;                                 \
        As[buf_][lk + 1][lrow]      = ra0.y;                                 \
        As[buf_][lk + 2][lrow]      = ra0.z;                                 \
        As[buf_][lk + 3][lrow]      = ra0.w;                                 \
        As[buf_][lk + 0][lrow + 64] = ra1.x;                                 \
        As[buf_][lk + 1][lrow + 64] = ra1.y;                                 \
        As[buf_][lk + 2][lrow + 64] = ra1.z;                                 \
        As[buf_][lk + 3][lrow + 64] = ra1.w;                                 \
        B0s[buf_][lk + 0][lrow] = rb0.x;                                     \
        B0s[buf_][lk + 1][lrow] = rb0.y;                                     \
        B0s[buf_][lk + 2][lrow] = rb0.z;                                     \
        B0s[buf_][lk + 3][lrow] = rb0.w;                                     \
        if (FUSED) {                                                         \
            B1s[buf_][lk + 0][lrow] = rb1.x;                                 \
            B1s[buf_][lk + 1][lrow] = rb1.y;                                 \
            B1s[buf_][lk + 2][lrow] = rb1.z;                                 \
            B1s[buf_][lk + 3][lrow] = rb1.w;                                 \
        }                                                                    \
    } while (0)

    unsigned long long acc0[8][2];
    unsigned long long acc1[FUSED ? 8 : 1][2];
#pragma unroll
    for (int i = 0; i < 8; ++i) { acc0[i][0] = 0ULL; acc0[i][1] = 0ULL; }
#pragma unroll
    for (int i = 0; i < (FUSED ? 8 : 1); ++i) { acc1[i][0] = 0ULL; acc1[i][1] = 0ULL; }

    LDG_TILE(0);
    STS_TILE(0);
    __syncthreads();

    constexpr int KT = K / BK;
    int cur = 0;
    for (int kt = 0; kt < KT; ++kt) {
        if (kt + 1 < KT) LDG_TILE(kt + 1);   // overlap next-tile loads w/ compute

#pragma unroll
        for (int kk = 0; kk < BK; ++kk) {
            float4 av0 = *reinterpret_cast<const float4*>(&As[cur][kk][ty * 8]);
            float4 av1 = *reinterpret_cast<const float4*>(&As[cur][kk][ty * 8 + 4]);
            float4 b0  = *reinterpret_cast<const float4*>(&B0s[cur][kk][tx * 4]);
            unsigned long long b0p0 = f2pk(b0.x, b0.y);
            unsigned long long b0p1 = f2pk(b0.z, b0.w);
            unsigned long long b1p0 = 0ULL, b1p1 = 0ULL;
            if (FUSED) {
                float4 b1 = *reinterpret_cast<const float4*>(&B1s[cur][kk][tx * 4]);
                b1p0 = f2pk(b1.x, b1.y);
                b1p1 = f2pk(b1.z, b1.w);
            }
            float a[8] = {av0.x, av0.y, av0.z, av0.w, av1.x, av1.y, av1.z, av1.w};
#pragma unroll
            for (int i = 0; i < 8; ++i) {
                unsigned long long aa = f2pk(a[i], a[i]);
                ffma2(acc0[i][0], aa, b0p0);
                ffma2(acc0[i][1], aa, b0p1);
                if (FUSED) {
                    ffma2(acc1[i][0], aa, b1p0);
                    ffma2(acc1[i][1], aa, b1p1);
                }
            }
        }

        if (kt + 1 < KT) {
            STS_TILE(cur ^ 1);     // write the *other* buffer: no WAR on cur
            __syncthreads();       // make it visible before next compute
            cur ^= 1;
        }
    }

    if (FUSED) {
#pragma unroll
        for (int i = 0; i < 8; ++i) {
            float2 g0 = f2un(acc0[i][0]);
            float2 g1 = f2un(acc0[i][1]);
            float2 u0 = f2un(acc1[i][0]);
            float2 u1 = f2un(acc1[i][1]);
            float4 h;
            h.x = silu_f(g0.x) * u0.x;
            h.y = silu_f(g0.y) * u0.y;
            h.z = silu_f(g1.x) * u1.x;
            h.w = silu_f(g1.y) * u1.y;
            *reinterpret_cast<float4*>(
                &g_Hid[(size_t)(mBase + ty * 8 + i) * I_DIM + nBase + tx * 4]) = h;
        }
    } else {
#pragma unroll
        for (int i = 0; i < 8; ++i) {
            int token = g_perm[mBase + ty * 8 + i];
            if (token >= 0) {
                float2 c0 = f2un(acc0[i][0]);
                float2 c1 = f2un(acc0[i][1]);
                float4 v = make_float4(c0.x, c0.y, c1.x, c1.y);
                *reinterpret_cast<float4*>(
                    &Out[(size_t)token * H_DIM + nBase + tx * 4]) = v;
            }
        }
    }
#undef LDG_TILE
#undef STS_TILE
}

// ---------------------------------------------------------------------------
// Launch: all kernels on the default stream, graph-capturable, no allocs.
// ---------------------------------------------------------------------------
extern "C" void kernel_launch(void* const* d_in, const int* in_sizes, int n_in,
                              void* d_out, int out_size) {
    (void)in_sizes; (void)n_in; (void)out_size;
    const float* x   = (const float*)d_in[0];
    const int*   idx = (const int*)d_in[1];
    const float* Wg  = (const float*)d_in[2];
    const float* Wu  = (const float*)d_in[3];
    const float* Wd  = (const float*)d_in[4];
    float* out = (float*)d_out;

    k_init   <<<(PADDED + 255) / 256, 256>>>();
    k_count  <<<T_TOK / 256, 256>>>(idx);
    k_scan   <<<1, 32>>>();
    k_scatter<<<T_TOK / 256, 256>>>(idx);
    k_gather <<<PADDED, 256>>>(x);

    dim3 g1(I_DIM / BN, MAX_TILES);   // 44 x 72
    k_gemm<true,  H_DIM, I_DIM><<<g1, 256>>>(Wg, Wu, nullptr);

    dim3 g2(H_DIM / BN, MAX_TILES);   // 16 x 72
    k_gemm<false, I_DIM, H_DIM><<<g2, 256>>>(Wd, nullptr, out);
}

// round 8
// speedup vs baseline: 1.7920x; 1.7920x over previous
#include <cuda_runtime.h>
#include <cuda_bf16.h>
#include <cstdint>
#include <cstddef>

typedef __nv_bfloat16 bf16;

// Problem constants (T,H,I,E = 8192,1024,2816,8)
#define T_TOK 8192
#define H_DIM 1024
#define I_DIM 2816
#define N_EXP 8
#define BM 128
#define BN 64
#define BKE 64                              // K elems per chunk
#define MAX_TILES ((T_TOK / BM) + N_EXP)    // 72
#define PADDED    (MAX_TILES * BM)          // 9216

// ---------------------------------------------------------------------------
// Device scratch. TOTAL = 141.6 MB, byte-identical to the R2 kernel that
// PASSED the harness memory guard (weight hi/lo copies eliminated: weights
// are now converted in-kernel from the fp32 inputs, which is bandwidth-equal).
// ---------------------------------------------------------------------------
__device__ int  g_counts[N_EXP];
__device__ int  g_wpos[N_EXP];
__device__ int  g_tile_expert[MAX_TILES];
__device__ int  g_perm[PADDED];
__device__ bf16 g_Xh[(size_t)PADDED * H_DIM];   // 18.9 MB
__device__ bf16 g_Xl[(size_t)PADDED * H_DIM];   // 18.9 MB
__device__ bf16 g_Hh[(size_t)PADDED * I_DIM];   // 51.9 MB
__device__ bf16 g_Hl[(size_t)PADDED * I_DIM];   // 51.9 MB

// ---------------------------------------------------------------------------
// PTX helpers — all non-arch-conditional (compute_100-legal):
// cp.async (sm_80), ldmatrix (sm_75), mma.sync bf16 (sm_80), cvt.bf16x2 (sm_80).
// ---------------------------------------------------------------------------
__device__ __forceinline__ uint32_t smem_u32(const void* p) {
    uint32_t a;
    asm("{ .reg .u64 t; cvta.to.shared.u64 t, %1; cvt.u32.u64 %0, t; }"
        : "=r"(a) : "l"(p));
    return a;
}
__device__ __forceinline__ void cp_async16(uint32_t dst, const void* src) {
    asm volatile("cp.async.cg.shared.global [%0], [%1], 16;"
                 :: "r"(dst), "l"(src) : "memory");
}
#define CP_ASYNC_COMMIT() asm volatile("cp.async.commit_group;" ::: "memory")
#define CP_ASYNC_WAIT0()  asm volatile("cp.async.wait_group 0;" ::: "memory")

#define LDSM4(r, addr) \
    asm volatile("ldmatrix.sync.aligned.m8n8.x4.shared.b16 {%0,%1,%2,%3}, [%4];" \
        : "=r"((r)[0]), "=r"((r)[1]), "=r"((r)[2]), "=r"((r)[3]) : "r"(addr))

#define STS128(addr, w0, w1, w2, w3) \
    asm volatile("st.shared.v4.b32 [%0], {%1,%2,%3,%4};" \
        :: "r"(addr), "r"(w0), "r"(w1), "r"(w2), "r"(w3) : "memory")

// D(16x8,f32) += A(16x16,bf16 row) * B(16x8,bf16 col); d compile-time indexed.
#define MMA_BF16(d, a, b0_, b1_) \
    asm volatile("mma.sync.aligned.m16n8k16.row.col.f32.bf16.bf16.f32 " \
        "{%0,%1,%2,%3}, {%4,%5,%6,%7}, {%8,%9}, {%0,%1,%2,%3};" \
        : "+f"((d)[0]), "+f"((d)[1]), "+f"((d)[2]), "+f"((d)[3]) \
        : "r"((a)[0]), "r"((a)[1]), "r"((a)[2]), "r"((a)[3]), "r"(b0_), "r"(b1_))

// pack two fp32 -> bf16x2 word (lo -> bits[15:0], hi -> bits[31:16])
__device__ __forceinline__ uint32_t cvt2(float lo, float hi) {
    uint32_t r;
    asm("cvt.rn.bf16x2.f32 %0, %1, %2;" : "=r"(r) : "f"(hi), "f"(lo));
    return r;
}
// hi/lo bf16 split of a float pair: wh = packed hi parts, wl = packed residuals
__device__ __forceinline__ void split2(float f0, float f1,
                                       uint32_t& wh, uint32_t& wl) {
    wh = cvt2(f0, f1);
    float h0 = __uint_as_float(wh << 16);
    float h1 = __uint_as_float(wh & 0xFFFF0000u);
    wl = cvt2(f0 - h0, f1 - h1);
}
__device__ __forceinline__ void split_bf(float v, bf16& h, bf16& l) {
    h = __float2bfloat16(v);
    l = __float2bfloat16(v - __bfloat162float(h));
}
__device__ __forceinline__ uint32_t pk2(bf16 a, bf16 b) {
    __nv_bfloat162 t = __halves2bfloat162(a, b);
    return *reinterpret_cast<uint32_t*>(&t);
}
__device__ __forceinline__ float silu_f(float v) { return v / (1.0f + __expf(-v)); }

// ---------------------------------------------------------------------------
// Permutation build
// ---------------------------------------------------------------------------
__global__ void k_init() {
    int i = blockIdx.x * blockDim.x + threadIdx.x;
    if (i < PADDED) g_perm[i] = -1;
    if (i < N_EXP)  g_counts[i] = 0;
}
__global__ void k_count(const int* __restrict__ idx) {
    int t = blockIdx.x * blockDim.x + threadIdx.x;
    if (t < T_TOK) atomicAdd(&g_counts[idx[t]], 1);
}
__global__ void k_scan() {
    if (threadIdx.x == 0 && blockIdx.x == 0) {
        int base = 0, tile = 0;
        for (int e = 0; e < N_EXP; ++e) {
            g_wpos[e] = base;
            int nt = (g_counts[e] + BM - 1) / BM;
            for (int i = 0; i < nt; ++i) g_tile_expert[tile++] = e;
            base += nt * BM;
        }
        for (; tile < MAX_TILES; ++tile) g_tile_expert[tile] = -1;   // dead tiles
    }
}
__global__ void k_scatter(const int* __restrict__ idx) {
    int t = blockIdx.x * blockDim.x + threadIdx.x;
    if (t < T_TOK) {
        int p = atomicAdd(&g_wpos[idx[t]], 1);
        g_perm[p] = t;
    }
}
// Gather tokens (grouped order) and split fp32 -> bf16 hi/lo. Padding -> zeros.
__global__ void k_gather_cvt(const float* __restrict__ x) {
    int row = blockIdx.x;
    int t = g_perm[row];
    int j = threadIdx.x;                 // 256 threads, one float4 each (H=1024)
    float4 v = make_float4(0.f, 0.f, 0.f, 0.f);
    if (t >= 0) v = reinterpret_cast<const float4*>(x + (size_t)t * H_DIM)[j];
    uint32_t h0, l0, h1, l1;
    split2(v.x, v.y, h0, l0);
    split2(v.z, v.w, h1, l1);
    size_t o = (size_t)row * H_DIM + j * 4;
    *reinterpret_cast<uint2*>(g_Xh + o) = make_uint2(h0, h1);
    *reinterpret_cast<uint2*>(g_Xl + o) = make_uint2(l0, l1);
}

// ---------------------------------------------------------------------------
// Grouped GEMM on legacy tensor cores (mma.sync m16n8k16 bf16, fp32 accum),
// split-bf16: C = Ah*Bh + Ah*Bl + Al*Bh.
//
// A: preconverted bf16 hi/lo in device globals, staged via cp.async.
// B: fp32 weights straight from the input tensors — LDG -> split -> STS
//    (same global bytes as preconverted hi/lo; zero static footprint).
//
// FUSED=true : A = Xh/Xl [PADDED,1024]; B = Wg rows (64) + Wu rows (64);
//              epilogue Hid = silu(g)*u -> split -> g_Hh/g_Hl.
// FUSED=false: A = Hh/Hl [PADDED,2816]; B = Wd rows (64);
//              epilogue scatters fp32 rows to out via g_perm.
//
// 256 threads = 8 warps (4M x 2N), warp tile 32x32 per C.
// 2-stage double buffer; SMEM rows 128B, XOR-16B swizzle; ldmatrix.x4.
// Stage layout: A_H 0, A_L 16K, B_H 32K, B_L 32K+Btile.
// ---------------------------------------------------------------------------
template <bool FUSED>
__global__ __launch_bounds__(256, 1)
void k_gemm_mma(const float* __restrict__ W0,   // Wg | Wd
                const float* __restrict__ W1,   // Wu | (unused)
                float* __restrict__ out) {
    extern __shared__ char smem[];
    const uint32_t sb = smem_u32(smem);

    constexpr int KTOT = FUSED ? H_DIM : I_DIM;
    constexpr int KT   = KTOT / BKE;                       // 16 | 44
    constexpr int BROWS = FUSED ? 128 : 64;                // B tile rows
    constexpr uint32_t OFF_AL = 16384u;
    constexpr uint32_t OFF_BH = 32768u;
    constexpr uint32_t BTILE  = (uint32_t)BROWS * 128u;    // 16K | 8K
    constexpr uint32_t OFF_BL = OFF_BH + BTILE;
    constexpr uint32_t STAGE  = OFF_BL + BTILE;            // 64K | 48K

    const int tid = threadIdx.x;
    const int wid = tid >> 5;
    const int lid = tid & 31;

    const int mt_blk = blockIdx.x;                         // mt fastest: weight
    const int expert = g_tile_expert[mt_blk];              // tiles shared in L2
    if (expert < 0) return;                                // dead tile
    const int mBase = mt_blk * BM;
    const int nBase = blockIdx.y * BN;

    const bf16* __restrict__ Ah = FUSED ? g_Xh : g_Hh;
    const bf16* __restrict__ Al = FUSED ? g_Xl : g_Hl;

    // ---- A fill geometry (cp.async bf16) ----
    const int r0  = tid >> 3;                              // 0..31
    const int seg = tid & 7;                               // 0..7
    const uint32_t swf = ((uint32_t)(seg ^ (r0 & 7))) << 4;

    // ---- B fill geometry (LDG fp32 -> split -> STS) ----
    // FUSED: brow 0..127 (gate 0-63, up 64-127), bhalf selects k 0-31|32-63.
    // DOWN : brow 0..63, bq selects 16-elem quarter.
    const int brow  = FUSED ? (tid >> 1) : (tid >> 2);
    const int bsub  = FUSED ? (tid & 1)  : (tid & 3);
    const int bkoff = FUSED ? bsub * 32  : bsub * 16;
    constexpr int BF = FUSED ? 32 : 16;                    // floats per thread

    const float* bsrc;
    if (FUSED) {
        const float* W = (brow < 64) ? W0 : W1;
        bsrc = W + ((size_t)expert * I_DIM + nBase + (brow & 63)) * H_DIM + bkoff;
    } else {
        bsrc = W0 + ((size_t)expert * H_DIM + nBase + brow) * I_DIM + bkoff;
    }
    const uint32_t bseg0 = (uint32_t)(bkoff >> 3);         // first 16B seg index
    const uint32_t brsw  = (uint32_t)(brow & 7);
    const uint32_t bbase = (uint32_t)brow * 128u;

    float fb[BF];                                          // fp32 B staging

    auto ldgB = [&](int c) {
        const float* s = bsrc + c * BKE;
#pragma unroll
        for (int i = 0; i < BF / 4; ++i) {
            float4 v = reinterpret_cast<const float4*>(s)[i];
            fb[i * 4 + 0] = v.x; fb[i * 4 + 1] = v.y;
            fb[i * 4 + 2] = v.z; fb[i * 4 + 3] = v.w;
        }
    };
    auto stsB = [&](uint32_t stg) {
#pragma unroll
        for (int q = 0; q < BF / 8; ++q) {                 // one 16B seg per q
            uint32_t wh[4], wl[4];
#pragma unroll
            for (int p = 0; p < 4; ++p)
                split2(fb[q * 8 + p * 2], fb[q * 8 + p * 2 + 1], wh[p], wl[p]);
            uint32_t d = bbase + (((bseg0 + q) ^ brsw) << 4);
            STS128(stg + OFF_BH + d, wh[0], wh[1], wh[2], wh[3]);
            STS128(stg + OFF_BL + d, wl[0], wl[1], wl[2], wl[3]);
        }
    };
    auto cpA = [&](int c, uint32_t stg) {
        const int k0 = c * BKE;
#pragma unroll
        for (int i = 0; i < 4; ++i) {
            int r = r0 + 32 * i;
            size_t ao = (size_t)(mBase + r) * KTOT + k0 + seg * 8;
            uint32_t d = (uint32_t)r * 128u + swf;
            cp_async16(stg + 0u     + d, Ah + ao);
            cp_async16(stg + OFF_AL + d, Al + ao);
        }
        CP_ASYNC_COMMIT();
    };

    // ---- ldmatrix lane geometry ----
    const int wm = wid >> 1;                               // 0..3 M
    const int wn = wid & 1;                                // 0..1 N
    const uint32_t lrow = (uint32_t)(lid & 15);
    const uint32_t lseg = (uint32_t)(lid >> 4);
    const uint32_t lxor = lrow & 7;

    float acc_g[2][4][4];
    float acc_u[FUSED ? 2 : 1][FUSED ? 4 : 1][4];
#pragma unroll
    for (int a = 0; a < 2; ++a)
#pragma unroll
        for (int b = 0; b < 4; ++b)
#pragma unroll
            for (int c = 0; c < 4; ++c) acc_g[a][b][c] = 0.f;
#pragma unroll
    for (int a = 0; a < (FUSED ? 2 : 1); ++a)
#pragma unroll
        for (int b = 0; b < (FUSED ? 4 : 1); ++b)
#pragma unroll
            for (int c = 0; c < 4; ++c) acc_u[a][b][c] = 0.f;

    // ---- prologue ----
    ldgB(0);
    cpA(0, sb);
    stsB(sb);
    CP_ASYNC_WAIT0();
    __syncthreads();

    // ---- main loop: 2-stage double buffer ----
    for (int c = 0; c < KT; ++c) {
        const uint32_t cur = sb + (uint32_t)(c & 1) * STAGE;
        const uint32_t nxt = sb + (uint32_t)((c + 1) & 1) * STAGE;
        const bool more = (c + 1 < KT);
        if (more) { ldgB(c + 1); cpA(c + 1, nxt); }        // DMA + LDG overlap

#pragma unroll
        for (int ks = 0; ks < 4; ++ks) {
            const uint32_t segx = (((uint32_t)(ks * 2) + lseg) ^ lxor) << 4;

            uint32_t aH[2][4], aL[2][4];
#pragma unroll
            for (int mt = 0; mt < 2; ++mt) {
                uint32_t off = ((uint32_t)(wm * 32 + mt * 16) + lrow) * 128u + segx;
                LDSM4(aH[mt], cur + 0u     + off);
                LDSM4(aL[mt], cur + OFF_AL + off);
            }

            uint32_t bh[2][4], bl[2][4];
#pragma unroll
            for (int grp = 0; grp < 2; ++grp) {            // gate | down region
                uint32_t off = ((uint32_t)(wn * 32 + grp * 16) + lrow) * 128u + segx;
                LDSM4(bh[grp], cur + OFF_BH + off);
                LDSM4(bl[grp], cur + OFF_BL + off);
            }
#pragma unroll
            for (int mt = 0; mt < 2; ++mt)
#pragma unroll
                for (int grp = 0; grp < 2; ++grp)
#pragma unroll
                    for (int half = 0; half < 2; ++half) {
                        MMA_BF16(acc_g[mt][grp * 2 + half], aH[mt],
                                 bh[grp][half], bh[grp][half + 2]);        // hh
                        MMA_BF16(acc_g[mt][grp * 2 + half], aH[mt],
                                 bl[grp][half], bl[grp][half + 2]);        // hl
                        MMA_BF16(acc_g[mt][grp * 2 + half], aL[mt],
                                 bh[grp][half], bh[grp][half + 2]);        // lh
                    }

            if (FUSED) {                                   // up region (rows 64+)
#pragma unroll
                for (int grp = 0; grp < 2; ++grp) {
                    uint32_t off = ((uint32_t)(64 + wn * 32 + grp * 16) + lrow) * 128u + segx;
                    LDSM4(bh[grp], cur + OFF_BH + off);
                    LDSM4(bl[grp], cur + OFF_BL + off);
                }
#pragma unroll
                for (int mt = 0; mt < 2; ++mt)
#pragma unroll
                    for (int grp = 0; grp < 2; ++grp)
#pragma unroll
                        for (int half = 0; half < 2; ++half) {
                            MMA_BF16(acc_u[mt][grp * 2 + half], aH[mt],
                                     bh[grp][half], bh[grp][half + 2]);    // hh
                            MMA_BF16(acc_u[mt][grp * 2 + half], aH[mt],
                                     bl[grp][half], bl[grp][half + 2]);    // hl
                            MMA_BF16(acc_u[mt][grp * 2 + half], aL[mt],
                                     bh[grp][half], bh[grp][half + 2]);    // lh
                        }
            }
        }

        if (more) {
            stsB(nxt);                    // regs(c+1) -> next buffer
            CP_ASYNC_WAIT0();             // A(c+1) landed
            __syncthreads();              // everyone done reading cur; nxt visible
        }
    }

    // ---- epilogue ----
    const int rbase = mBase + wm * 32 + (lid >> 2);
    const int cbase = nBase + wn * 32 + (lid & 3) * 2;

    if (FUSED) {
#pragma unroll
        for (int mt = 0; mt < 2; ++mt)
#pragma unroll
            for (int nt = 0; nt < 4; ++nt)
#pragma unroll
                for (int hr = 0; hr < 2; ++hr) {
                    int row = rbase + mt * 16 + hr * 8;
                    int col = cbase + nt * 8;
                    float h0 = silu_f(acc_g[mt][nt][hr * 2 + 0]) *
                               acc_u[mt][nt][hr * 2 + 0];
                    float h1 = silu_f(acc_g[mt][nt][hr * 2 + 1]) *
                               acc_u[mt][nt][hr * 2 + 1];
                    bf16 h0h, h0l, h1h, h1l;
                    split_bf(h0, h0h, h0l);
                    split_bf(h1, h1h, h1l);
                    size_t o = (size_t)row * I_DIM + col;
                    *reinterpret_cast<uint32_t*>(g_Hh + o) = pk2(h0h, h1h);
                    *reinterpret_cast<uint32_t*>(g_Hl + o) = pk2(h0l, h1l);
                }
    } else {
#pragma unroll
        for (int mt = 0; mt < 2; ++mt)
#pragma unroll
            for (int hr = 0; hr < 2; ++hr) {
                int row = rbase + mt * 16 + hr * 8;
                int token = g_perm[row];
                if (token >= 0) {
#pragma unroll
                    for (int nt = 0; nt < 4; ++nt) {
                        int col = cbase + nt * 8;
                        *reinterpret_cast<float2*>(out + (size_t)token * H_DIM + col) =
                            make_float2(acc_g[mt][nt][hr * 2 + 0],
                                        acc_g[mt][nt][hr * 2 + 1]);
                    }
                }
            }
    }
}

// ---------------------------------------------------------------------------
// Launch (graph-capturable: kernel launches only)
// ---------------------------------------------------------------------------
extern "C" void kernel_launch(void* const* d_in, const int* in_sizes, int n_in,
                              void* d_out, int out_size) {
    (void)in_sizes; (void)n_in; (void)out_size;
    const float* x   = (const float*)d_in[0];
    const int*   idx = (const int*)d_in[1];
    const float* Wg  = (const float*)d_in[2];
    const float* Wu  = (const float*)d_in[3];
    const float* Wd  = (const float*)d_in[4];
    float* out = (float*)d_out;

    constexpr int SMEM1 = 2 * 65536;     // 128 KB (FUSED)
    constexpr int SMEM2 = 2 * 49152;     //  96 KB (DOWN)
    cudaFuncSetAttribute(k_gemm_mma<true>,
                         cudaFuncAttributeMaxDynamicSharedMemorySize, SMEM1);
    cudaFuncSetAttribute(k_gemm_mma<false>,
                         cudaFuncAttributeMaxDynamicSharedMemorySize, SMEM2);

    k_init   <<<(PADDED + 255) / 256, 256>>>();
    k_count  <<<T_TOK / 256, 256>>>(idx);
    k_scan   <<<1, 32>>>();
    k_scatter<<<T_TOK / 256, 256>>>(idx);
    k_gather_cvt<<<PADDED, 256>>>(x);

    // mt fastest (blockIdx.x) -> concurrent CTAs share weight tiles in L2
    dim3 g1(MAX_TILES, I_DIM / BN);               // 72 x 44
    k_gemm_mma<true><<<g1, 256, SMEM1>>>(Wg, Wu, nullptr);

    dim3 g2(MAX_TILES, H_DIM / BN);               // 72 x 16
    k_gemm_mma<false><<<g2, 256, SMEM2>>>(Wd, nullptr, out);
}

// round 10
// speedup vs baseline: 1.9204x; 1.0717x over previous
#include <cuda_runtime.h>
#include <cuda_bf16.h>
#include <cstdint>
#include <cstddef>

typedef __nv_bfloat16 bf16;

// Problem constants (T,H,I,E = 8192,1024,2816,8)
#define T_TOK 8192
#define H_DIM 1024
#define I_DIM 2816
#define N_EXP 8
#define BM 128
#define BN 64
#define BKE 64                              // K elems per chunk
#define MAX_TILES ((T_TOK / BM) + N_EXP)    // 72
#define PADDED    (MAX_TILES * BM)          // 9216

// ---------------------------------------------------------------------------
// Device scratch: 141.6 MB total — same footprint that passes the memory guard.
// ---------------------------------------------------------------------------
__device__ int  g_counts[N_EXP];
__device__ int  g_wpos[N_EXP];
__device__ int  g_tile_expert[MAX_TILES];
__device__ int  g_perm[PADDED];
__device__ bf16 g_Xh[(size_t)PADDED * H_DIM];   // 18.9 MB
__device__ bf16 g_Xl[(size_t)PADDED * H_DIM];   // 18.9 MB
__device__ bf16 g_Hh[(size_t)PADDED * I_DIM];   // 51.9 MB
__device__ bf16 g_Hl[(size_t)PADDED * I_DIM];   // 51.9 MB

// ---------------------------------------------------------------------------
// PTX helpers — all non-arch-conditional (compute_100-legal).
// ---------------------------------------------------------------------------
__device__ __forceinline__ uint32_t smem_u32(const void* p) {
    uint32_t a;
    asm("{ .reg .u64 t; cvta.to.shared.u64 t, %1; cvt.u32.u64 %0, t; }"
        : "=r"(a) : "l"(p));
    return a;
}
__device__ __forceinline__ void cp_async16(uint32_t dst, const void* src) {
    asm volatile("cp.async.cg.shared.global [%0], [%1], 16;"
                 :: "r"(dst), "l"(src) : "memory");
}
#define CP_ASYNC_COMMIT() asm volatile("cp.async.commit_group;" ::: "memory")
#define CP_ASYNC_WAIT0()  asm volatile("cp.async.wait_group 0;" ::: "memory")

#define LDSM4(r, addr) \
    asm volatile("ldmatrix.sync.aligned.m8n8.x4.shared.b16 {%0,%1,%2,%3}, [%4];" \
        : "=r"((r)[0]), "=r"((r)[1]), "=r"((r)[2]), "=r"((r)[3]) : "r"(addr))

#define STS128(addr, w0, w1, w2, w3) \
    asm volatile("st.shared.v4.b32 [%0], {%1,%2,%3,%4};" \
        :: "r"(addr), "r"(w0), "r"(w1), "r"(w2), "r"(w3) : "memory")

// D(16x8,f32) += A(16x16,bf16 row) * B(16x8,bf16 col); d compile-time indexed.
#define MMA_BF16(d, a, b0_, b1_) \
    asm volatile("mma.sync.aligned.m16n8k16.row.col.f32.bf16.bf16.f32 " \
        "{%0,%1,%2,%3}, {%4,%5,%6,%7}, {%8,%9}, {%0,%1,%2,%3};" \
        : "+f"((d)[0]), "+f"((d)[1]), "+f"((d)[2]), "+f"((d)[3]) \
        : "r"((a)[0]), "r"((a)[1]), "r"((a)[2]), "r"((a)[3]), "r"(b0_), "r"(b1_))

// pack two fp32 -> bf16x2 word (f0 -> bits[15:0], f1 -> bits[31:16])
__device__ __forceinline__ uint32_t cvt2(float lo, float hi) {
    uint32_t r;
    asm("cvt.rn.bf16x2.f32 %0, %1, %2;" : "=r"(r) : "f"(hi), "f"(lo));
    return r;
}
// hi/lo bf16 split of a float pair
__device__ __forceinline__ void split2(float f0, float f1,
                                       uint32_t& wh, uint32_t& wl) {
    wh = cvt2(f0, f1);
    float h0 = __uint_as_float(wh << 16);
    float h1 = __uint_as_float(wh & 0xFFFF0000u);
    wl = cvt2(f0 - h0, f1 - h1);
}
__device__ __forceinline__ void split_bf(float v, bf16& h, bf16& l) {
    h = __float2bfloat16(v);
    l = __float2bfloat16(v - __bfloat162float(h));
}
__device__ __forceinline__ uint32_t pk2(bf16 a, bf16 b) {
    __nv_bfloat162 t = __halves2bfloat162(a, b);
    return *reinterpret_cast<uint32_t*>(&t);
}
__device__ __forceinline__ float silu_f(float v) { return v / (1.0f + __expf(-v)); }

// ---------------------------------------------------------------------------
// Permutation build
// ---------------------------------------------------------------------------
__global__ void k_init() {
    int i = blockIdx.x * blockDim.x + threadIdx.x;
    if (i < PADDED) g_perm[i] = -1;
    if (i < N_EXP)  g_counts[i] = 0;
}
__global__ void k_count(const int* __restrict__ idx) {
    int t = blockIdx.x * blockDim.x + threadIdx.x;
    if (t < T_TOK) atomicAdd(&g_counts[idx[t]], 1);
}
__global__ void k_scan() {
    if (threadIdx.x == 0 && blockIdx.x == 0) {
        int base = 0, tile = 0;
        for (int e = 0; e < N_EXP; ++e) {
            g_wpos[e] = base;
            int nt = (g_counts[e] + BM - 1) / BM;
            for (int i = 0; i < nt; ++i) g_tile_expert[tile++] = e;
            base += nt * BM;
        }
        for (; tile < MAX_TILES; ++tile) g_tile_expert[tile] = -1;   // dead tiles
    }
}
__global__ void k_scatter(const int* __restrict__ idx) {
    int t = blockIdx.x * blockDim.x + threadIdx.x;
    if (t < T_TOK) {
        int p = atomicAdd(&g_wpos[idx[t]], 1);
        g_perm[p] = t;
    }
}
// Gather tokens (grouped order) and split fp32 -> bf16 hi/lo. Padding -> zeros.
__global__ void k_gather_cvt(const float* __restrict__ x) {
    int row = blockIdx.x;
    int t = g_perm[row];
    int j = threadIdx.x;                 // 256 threads, one float4 each (H=1024)
    float4 v = make_float4(0.f, 0.f, 0.f, 0.f);
    if (t >= 0) v = reinterpret_cast<const float4*>(x + (size_t)t * H_DIM)[j];
    uint32_t h0, l0, h1, l1;
    split2(v.x, v.y, h0, l0);
    split2(v.z, v.w, h1, l1);
    size_t o = (size_t)row * H_DIM + j * 4;
    *reinterpret_cast<uint2*>(g_Xh + o) = make_uint2(h0, h1);
    *reinterpret_cast<uint2*>(g_Xl + o) = make_uint2(l0, l1);
}

// ---------------------------------------------------------------------------
// Grouped GEMM on legacy tensor cores (mma.sync m16n8k16 bf16, fp32 accum),
// split-bf16: C = Ah*Bh + Ah*Bl + Al*Bh.
//
// A: preconverted bf16 hi/lo globals, staged via cp.async.
// B: fp32 weights from the inputs — LDG -> split -> STS (bandwidth-equal).
//
// 512 threads = 16 warps as 4(M) x 4(N); warp tile 32x16 per C matrix.
// (4 warps/SMSP: hides HMMA latency, sync barriers, and LDSM bursts that
//  capped the 8-warp version at ~60% of the tensor roofline.)
// 2-stage double buffer; SMEM rows 128B, XOR-16B swizzle; ldmatrix.x4.
// Stage layout: A_H 0, A_L 16K, B_H 32K, B_L 32K+Btile.
// ---------------------------------------------------------------------------
template <bool FUSED>
__global__ __launch_bounds__(512, 1)
void k_gemm_mma(const float* __restrict__ W0,   // Wg | Wd
                const float* __restrict__ W1,   // Wu | (unused)
                float* __restrict__ out) {
    extern __shared__ char smem[];
    const uint32_t sb = smem_u32(smem);

    constexpr int KTOT = FUSED ? H_DIM : I_DIM;
    constexpr int KT   = KTOT / BKE;                       // 16 | 44
    constexpr int BROWS = FUSED ? 128 : 64;                // B tile rows
    constexpr uint32_t OFF_AL = 16384u;
    constexpr uint32_t OFF_BH = 32768u;
    constexpr uint32_t BTILE  = (uint32_t)BROWS * 128u;    // 16K | 8K
    constexpr uint32_t OFF_BL = OFF_BH + BTILE;
    constexpr uint32_t STAGE  = OFF_BL + BTILE;            // 64K | 48K

    const int tid = threadIdx.x;
    const int wid = tid >> 5;
    const int lid = tid & 31;

    const int mt_blk = blockIdx.x;                         // mt fastest: weight
    const int expert = g_tile_expert[mt_blk];              // tiles shared in L2
    if (expert < 0) return;                                // dead tile
    const int mBase = mt_blk * BM;
    const int nBase = blockIdx.y * BN;

    const bf16* __restrict__ Ah = FUSED ? g_Xh : g_Hh;
    const bf16* __restrict__ Al = FUSED ? g_Xl : g_Hl;

    // ---- A fill geometry (cp.async bf16): 512 thr -> 64 rows/pass, 2 passes
    const int r0  = tid >> 3;                              // 0..63
    const int seg = tid & 7;                               // 0..7
    const uint32_t swf = ((uint32_t)(seg ^ (r0 & 7))) << 4;

    // ---- B fill geometry (LDG fp32 -> split -> STS) ----
    // FUSED: 128 rows, 4 thr/row, 16 floats each. DOWN: 64 rows, 8 thr/row, 8 floats.
    const int brow  = FUSED ? (tid >> 2) : (tid >> 3);
    const int bsub  = FUSED ? (tid & 3)  : (tid & 7);
    const int bkoff = FUSED ? bsub * 16  : bsub * 8;
    constexpr int BF = FUSED ? 16 : 8;                     // floats per thread

    const float* bsrc;
    if (FUSED) {
        const float* W = (brow < 64) ? W0 : W1;
        bsrc = W + ((size_t)expert * I_DIM + nBase + (brow & 63)) * H_DIM + bkoff;
    } else {
        bsrc = W0 + ((size_t)expert * H_DIM + nBase + brow) * I_DIM + bkoff;
    }
    const uint32_t bseg0 = (uint32_t)(bkoff >> 3);         // first bf16 16B-seg
    const uint32_t brsw  = (uint32_t)(brow & 7);
    const uint32_t bbase = (uint32_t)brow * 128u;

    float fb[BF];                                          // fp32 B staging

    auto ldgB = [&](int c) {
        const float* s = bsrc + c * BKE;
#pragma unroll
        for (int i = 0; i < BF / 4; ++i) {
            float4 v = reinterpret_cast<const float4*>(s)[i];
            fb[i * 4 + 0] = v.x; fb[i * 4 + 1] = v.y;
            fb[i * 4 + 2] = v.z; fb[i * 4 + 3] = v.w;
        }
    };
    auto stsB = [&](uint32_t stg) {
#pragma unroll
        for (int q = 0; q < BF / 8; ++q) {                 // one 16B seg per q
            uint32_t wh[4], wl[4];
#pragma unroll
            for (int p = 0; p < 4; ++p)
                split2(fb[q * 8 + p * 2], fb[q * 8 + p * 2 + 1], wh[p], wl[p]);
            uint32_t d = bbase + (((bseg0 + q) ^ brsw) << 4);
            STS128(stg + OFF_BH + d, wh[0], wh[1], wh[2], wh[3]);
            STS128(stg + OFF_BL + d, wl[0], wl[1], wl[2], wl[3]);
        }
    };
    auto cpA = [&](int c, uint32_t stg) {
        const int k0 = c * BKE;
#pragma unroll
        for (int i = 0; i < 2; ++i) {
            int r = r0 + 64 * i;
            size_t ao = (size_t)(mBase + r) * KTOT + k0 + seg * 8;
            uint32_t d = (uint32_t)r * 128u + swf;
            cp_async16(stg + 0u     + d, Ah + ao);
            cp_async16(stg + OFF_AL + d, Al + ao);
        }
        CP_ASYNC_COMMIT();
    };

    // ---- ldmatrix lane geometry ----
    const int wm = wid >> 2;                               // 0..3 : M * 32
    const int wn = wid & 3;                                // 0..3 : N * 16
    const uint32_t lrow = (uint32_t)(lid & 15);
    const uint32_t lseg = (uint32_t)(lid >> 4);
    const uint32_t lxor = lrow & 7;

    float acc_g[2][2][4];                                  // [mt][n8][4]
    float acc_u[FUSED ? 2 : 1][FUSED ? 2 : 1][4];
#pragma unroll
    for (int a = 0; a < 2; ++a)
#pragma unroll
        for (int b = 0; b < 2; ++b)
#pragma unroll
            for (int c = 0; c < 4; ++c) acc_g[a][b][c] = 0.f;
#pragma unroll
    for (int a = 0; a < (FUSED ? 2 : 1); ++a)
#pragma unroll
        for (int b = 0; b < (FUSED ? 2 : 1); ++b)
#pragma unroll
            for (int c = 0; c < 4; ++c) acc_u[a][b][c] = 0.f;

    // ---- prologue ----
    ldgB(0);
    cpA(0, sb);
    stsB(sb);
    CP_ASYNC_WAIT0();
    __syncthreads();

    // ---- main loop: 2-stage double buffer ----
    for (int c = 0; c < KT; ++c) {
        const uint32_t cur = sb + (uint32_t)(c & 1) * STAGE;
        const uint32_t nxt = sb + (uint32_t)((c + 1) & 1) * STAGE;
        const bool more = (c + 1 < KT);
        if (more) { ldgB(c + 1); cpA(c + 1, nxt); }        // overlap with compute

#pragma unroll
        for (int ks = 0; ks < 4; ++ks) {
            const uint32_t segx = (((uint32_t)(ks * 2) + lseg) ^ lxor) << 4;

            uint32_t aH[2][4], aL[2][4];
#pragma unroll
            for (int mt = 0; mt < 2; ++mt) {
                uint32_t off = ((uint32_t)(wm * 32 + mt * 16) + lrow) * 128u + segx;
                LDSM4(aH[mt], cur + 0u     + off);
                LDSM4(aL[mt], cur + OFF_AL + off);
            }

            uint32_t bh[4], bl[4];
            {   // gate (FUSED) / down (!FUSED): rows wn*16..wn*16+15
                uint32_t off = ((uint32_t)(wn * 16) + lrow) * 128u + segx;
                LDSM4(bh, cur + OFF_BH + off);
                LDSM4(bl, cur + OFF_BL + off);
            }
#pragma unroll
            for (int mt = 0; mt < 2; ++mt)
#pragma unroll
                for (int half = 0; half < 2; ++half) {
                    MMA_BF16(acc_g[mt][half], aH[mt], bh[half], bh[half + 2]); // hh
                    MMA_BF16(acc_g[mt][half], aH[mt], bl[half], bl[half + 2]); // hl
                    MMA_BF16(acc_g[mt][half], aL[mt], bh[half], bh[half + 2]); // lh
                }

            if (FUSED) {   // up region: rows 64 + wn*16 ..
                uint32_t off = ((uint32_t)(64 + wn * 16) + lrow) * 128u + segx;
                LDSM4(bh, cur + OFF_BH + off);
                LDSM4(bl, cur + OFF_BL + off);
#pragma unroll
                for (int mt = 0; mt < 2; ++mt)
#pragma unroll
                    for (int half = 0; half < 2; ++half) {
                        MMA_BF16(acc_u[mt][half], aH[mt], bh[half], bh[half + 2]);
                        MMA_BF16(acc_u[mt][half], aH[mt], bl[half], bl[half + 2]);
                        MMA_BF16(acc_u[mt][half], aL[mt], bh[half], bh[half + 2]);
                    }
            }
        }

        if (more) {
            stsB(nxt);                    // regs(c+1) -> next buffer
            CP_ASYNC_WAIT0();             // A(c+1) landed
            __syncthreads();              // cur fully read; nxt visible
        }
    }

    // ---- epilogue ----
    const int rbase = mBase + wm * 32 + (lid >> 2);
    const int cbase = nBase + wn * 16 + (lid & 3) * 2;

    if (FUSED) {
#pragma unroll
        for (int mt = 0; mt < 2; ++mt)
#pragma unroll
            for (int nt = 0; nt < 2; ++nt)
#pragma unroll
                for (int hr = 0; hr < 2; ++hr) {
                    int row = rbase + mt * 16 + hr * 8;
                    int col = cbase + nt * 8;
                    float h0 = silu_f(acc_g[mt][nt][hr * 2 + 0]) *
                               acc_u[mt][nt][hr * 2 + 0];
                    float h1 = silu_f(acc_g[mt][nt][hr * 2 + 1]) *
                               acc_u[mt][nt][hr * 2 + 1];
                    bf16 h0h, h0l, h1h, h1l;
                    split_bf(h0, h0h, h0l);
                    split_bf(h1, h1h, h1l);
                    size_t o = (size_t)row * I_DIM + col;
                    *reinterpret_cast<uint32_t*>(g_Hh + o) = pk2(h0h, h1h);
                    *reinterpret_cast<uint32_t*>(g_Hl + o) = pk2(h0l, h1l);
                }
    } else {
#pragma unroll
        for (int mt = 0; mt < 2; ++mt)
#pragma unroll
            for (int hr = 0; hr < 2; ++hr) {
                int row = rbase + mt * 16 + hr * 8;
                int token = g_perm[row];
                if (token >= 0) {
#pragma unroll
                    for (int nt = 0; nt < 2; ++nt) {
                        int col = cbase + nt * 8;
                        *reinterpret_cast<float2*>(out + (size_t)token * H_DIM + col) =
                            make_float2(acc_g[mt][nt][hr * 2 + 0],
                                        acc_g[mt][nt][hr * 2 + 1]);
                    }
                }
            }
    }
}

// ---------------------------------------------------------------------------
// Launch (graph-capturable: kernel launches only)
// ---------------------------------------------------------------------------
extern "C" void kernel_launch(void* const* d_in, const int* in_sizes, int n_in,
                              void* d_out, int out_size) {
    (void)in_sizes; (void)n_in; (void)out_size;
    const float* x   = (const float*)d_in[0];
    const int*   idx = (const int*)d_in[1];
    const float* Wg  = (const float*)d_in[2];
    const float* Wu  = (const float*)d_in[3];
    const float* Wd  = (const float*)d_in[4];
    float* out = (float*)d_out;

    constexpr int SMEM1 = 2 * 65536;     // 128 KB (FUSED)
    constexpr int SMEM2 = 2 * 49152;     //  96 KB (DOWN)
    cudaFuncSetAttribute(k_gemm_mma<true>,
                         cudaFuncAttributeMaxDynamicSharedMemorySize, SMEM1);
    cudaFuncSetAttribute(k_gemm_mma<false>,
                         cudaFuncAttributeMaxDynamicSharedMemorySize, SMEM2);

    k_init   <<<(PADDED + 255) / 256, 256>>>();
    k_count  <<<T_TOK / 256, 256>>>(idx);
    k_scan   <<<1, 32>>>();
    k_scatter<<<T_TOK / 256, 256>>>(idx);
    k_gather_cvt<<<PADDED, 256>>>(x);

    // mt fastest (blockIdx.x) -> concurrent CTAs share weight tiles in L2
    dim3 g1(MAX_TILES, I_DIM / BN);               // 72 x 44
    k_gemm_mma<true><<<g1, 512, SMEM1>>>(Wg, Wu, nullptr);

    dim3 g2(MAX_TILES, H_DIM / BN);               // 72 x 16
    k_gemm_mma<false><<<g2, 512, SMEM2>>>(Wd, nullptr, out);
}

// round 12
// speedup vs baseline: 2.0320x; 1.0581x over previous
#include <cuda_runtime.h>
#include <cuda_bf16.h>
#include <cstdint>
#include <cstddef>

typedef __nv_bfloat16 bf16;

// Problem constants (T,H,I,E = 8192,1024,2816,8)
#define T_TOK 8192
#define H_DIM 1024
#define I_DIM 2816
#define N_EXP 8
#define BM 128
#define BN 128
#define BKE 64                              // K elems per chunk
#define MAX_TILES ((T_TOK / BM) + N_EXP)    // 72
#define PADDED    (MAX_TILES * BM)          // 9216

// ---------------------------------------------------------------------------
// Device scratch: 141.6 MB total — the footprint that passes the memory guard.
// ---------------------------------------------------------------------------
__device__ int  g_counts[N_EXP];
__device__ int  g_wpos[N_EXP];
__device__ int  g_tile_expert[MAX_TILES];
__device__ int  g_perm[PADDED];
__device__ bf16 g_Xh[(size_t)PADDED * H_DIM];   // 18.9 MB
__device__ bf16 g_Xl[(size_t)PADDED * H_DIM];   // 18.9 MB
__device__ bf16 g_Hh[(size_t)PADDED * I_DIM];   // 51.9 MB
__device__ bf16 g_Hl[(size_t)PADDED * I_DIM];   // 51.9 MB

// ---------------------------------------------------------------------------
// PTX helpers — all non-arch-conditional (compute_100-legal).
// ---------------------------------------------------------------------------
__device__ __forceinline__ uint32_t smem_u32(const void* p) {
    uint32_t a;
    asm("{ .reg .u64 t; cvta.to.shared.u64 t, %1; cvt.u32.u64 %0, t; }"
        : "=r"(a) : "l"(p));
    return a;
}
__device__ __forceinline__ void cp_async16(uint32_t dst, const void* src) {
    asm volatile("cp.async.cg.shared.global [%0], [%1], 16;"
                 :: "r"(dst), "l"(src) : "memory");
}
#define CP_ASYNC_COMMIT() asm volatile("cp.async.commit_group;" ::: "memory")
#define CP_ASYNC_WAIT0()  asm volatile("cp.async.wait_group 0;" ::: "memory")

#define LDSM4(r, addr) \
    asm volatile("ldmatrix.sync.aligned.m8n8.x4.shared.b16 {%0,%1,%2,%3}, [%4];" \
        : "=r"((r)[0]), "=r"((r)[1]), "=r"((r)[2]), "=r"((r)[3]) : "r"(addr))

#define STS128(addr, w0, w1, w2, w3) \
    asm volatile("st.shared.v4.b32 [%0], {%1,%2,%3,%4};" \
        :: "r"(addr), "r"(w0), "r"(w1), "r"(w2), "r"(w3) : "memory")

// D(16x8,f32) += A(16x16,bf16 row) * B(16x8,bf16 col); d compile-time indexed.
#define MMA_BF16(d, a, b0_, b1_) \
    asm volatile("mma.sync.aligned.m16n8k16.row.col.f32.bf16.bf16.f32 " \
        "{%0,%1,%2,%3}, {%4,%5,%6,%7}, {%8,%9}, {%0,%1,%2,%3};" \
        : "+f"((d)[0]), "+f"((d)[1]), "+f"((d)[2]), "+f"((d)[3]) \
        : "r"((a)[0]), "r"((a)[1]), "r"((a)[2]), "r"((a)[3]), "r"(b0_), "r"(b1_))

// pack two fp32 -> bf16x2 word (f0 -> bits[15:0], f1 -> bits[31:16])
__device__ __forceinline__ uint32_t cvt2(float lo, float hi) {
    uint32_t r;
    asm("cvt.rn.bf16x2.f32 %0, %1, %2;" : "=r"(r) : "f"(hi), "f"(lo));
    return r;
}
// hi/lo bf16 split of a float pair
__device__ __forceinline__ void split2(float f0, float f1,
                                       uint32_t& wh, uint32_t& wl) {
    wh = cvt2(f0, f1);
    float h0 = __uint_as_float(wh << 16);
    float h1 = __uint_as_float(wh & 0xFFFF0000u);
    wl = cvt2(f0 - h0, f1 - h1);
}
__device__ __forceinline__ void split_bf(float v, bf16& h, bf16& l) {
    h = __float2bfloat16(v);
    l = __float2bfloat16(v - __bfloat162float(h));
}
__device__ __forceinline__ uint32_t pk2(bf16 a, bf16 b) {
    __nv_bfloat162 t = __halves2bfloat162(a, b);
    return *reinterpret_cast<uint32_t*>(&t);
}
__device__ __forceinline__ float silu_f(float v) { return v / (1.0f + __expf(-v)); }

// ---------------------------------------------------------------------------
// Permutation build
// ---------------------------------------------------------------------------
__global__ void k_init() {
    int i = blockIdx.x * blockDim.x + threadIdx.x;
    if (i < PADDED) g_perm[i] = -1;
    if (i < N_EXP)  g_counts[i] = 0;
}
__global__ void k_count(const int* __restrict__ idx) {
    int t = blockIdx.x * blockDim.x + threadIdx.x;
    if (t < T_TOK) atomicAdd(&g_counts[idx[t]], 1);
}
__global__ void k_scan() {
    if (threadIdx.x == 0 && blockIdx.x == 0) {
        int base = 0, tile = 0;
        for (int e = 0; e < N_EXP; ++e) {
            g_wpos[e] = base;
            int nt = (g_counts[e] + BM - 1) / BM;
            for (int i = 0; i < nt; ++i) g_tile_expert[tile++] = e;
            base += nt * BM;
        }
        for (; tile < MAX_TILES; ++tile) g_tile_expert[tile] = -1;   // dead tiles
    }
}
__global__ void k_scatter(const int* __restrict__ idx) {
    int t = blockIdx.x * blockDim.x + threadIdx.x;
    if (t < T_TOK) {
        int p = atomicAdd(&g_wpos[idx[t]], 1);
        g_perm[p] = t;
    }
}
// Gather tokens (grouped order) and split fp32 -> bf16 hi/lo. Padding -> zeros.
__global__ void k_gather_cvt(const float* __restrict__ x) {
    int row = blockIdx.x;
    int t = g_perm[row];
    int j = threadIdx.x;                 // 256 threads, one float4 each (H=1024)
    float4 v = make_float4(0.f, 0.f, 0.f, 0.f);
    if (t >= 0) v = reinterpret_cast<const float4*>(x + (size_t)t * H_DIM)[j];
    uint32_t h0, l0, h1, l1;
    split2(v.x, v.y, h0, l0);
    split2(v.z, v.w, h1, l1);
    size_t o = (size_t)row * H_DIM + j * 4;
    *reinterpret_cast<uint2*>(g_Xh + o) = make_uint2(h0, h1);
    *reinterpret_cast<uint2*>(g_Xl + o) = make_uint2(l0, l1);
}

// ---------------------------------------------------------------------------
// Grouped GEMM on legacy tensor cores (mma.sync m16n8k16 bf16, fp32 accum),
// split-bf16: C = Ah*Bh + Ah*Bl + Al*Bh.
//
// BN=128, warp tile 32x32 (4M x 4N, 16 warps): halves SMEM-crossbar bytes
// per MAC vs BN=64/32x16 (the co-binding resource identified in R9's
// post-mortem) and halves A-side L2 traffic.
//
// A: preconverted bf16 hi/lo globals via cp.async (rows 0..127 hi + lo).
// B: fp32 weights LDG -> split -> STS. FUSED fills 256 rows (gate 0..127,
//    up 128..255) in FOUR fb[8] passes interleaved after each ks so peak
//    registers stay < 128/thread (spill trips the harness memory guard).
//
// Stage layout: A_H 0, A_L 16K, B_H 32K, B_L 32K+BTILE.
//   FUSED: BTILE=32K, stage 96K x2 = 192K.  DOWN: BTILE=16K, stage 64K x2.
// ---------------------------------------------------------------------------
template <bool FUSED>
__global__ __launch_bounds__(512, 1)
void k_gemm_mma(const float* __restrict__ W0,   // Wg | Wd
                const float* __restrict__ W1,   // Wu | (unused)
                float* __restrict__ out) {
    extern __shared__ char smem[];
    const uint32_t sb = smem_u32(smem);

    constexpr int KTOT = FUSED ? H_DIM : I_DIM;
    constexpr int KT   = KTOT / BKE;                       // 16 | 44
    constexpr int BROWS = FUSED ? 256 : 128;               // B tile rows
    constexpr uint32_t OFF_AL = 16384u;
    constexpr uint32_t OFF_BH = 32768u;
    constexpr uint32_t BTILE  = (uint32_t)BROWS * 128u;    // 32K | 16K
    constexpr uint32_t OFF_BL = OFF_BH + BTILE;
    constexpr uint32_t STAGE  = OFF_BL + BTILE;            // 96K | 64K

    const int tid = threadIdx.x;
    const int wid = tid >> 5;
    const int lid = tid & 31;

    const int mt_blk = blockIdx.x;                         // mt fastest: weight
    const int expert = g_tile_expert[mt_blk];              // tiles shared in L2
    if (expert < 0) return;                                // dead tile
    const int mBase = mt_blk * BM;
    const int nBase = blockIdx.y * BN;

    const bf16* __restrict__ Ah = FUSED ? g_Xh : g_Hh;
    const bf16* __restrict__ Al = FUSED ? g_Xl : g_Hl;

    // ---- A fill geometry (cp.async bf16): 2 row-groups of 64 per thread ----
    const int r0  = tid >> 3;                              // 0..63
    const int seg = tid & 7;                               // 0..7
    const uint32_t swf = ((uint32_t)(seg ^ (r0 & 7))) << 4;

    auto cpA = [&](int c, uint32_t stg) {
        const int k0 = c * BKE;
#pragma unroll
        for (int i = 0; i < 2; ++i) {
            int r = r0 + 64 * i;
            size_t ao = (size_t)(mBase + r) * KTOT + k0 + seg * 8;
            uint32_t d = (uint32_t)r * 128u + swf;
            cp_async16(stg + 0u     + d, Ah + ao);
            cp_async16(stg + OFF_AL + d, Al + ao);
        }
        CP_ASYNC_COMMIT();
    };

    // ---- FUSED B fill: 4 passes, 64 rows x 8 floats/thread (fb[8]) ----
    // pass p covers rows [p*64, p*64+64): p<2 -> gate (W0), p>=2 -> up (W1).
    const int rB   = tid >> 3;                             // 0..63 row-in-pass
    const int sq   = tid & 7;                              // 16B seg 0..7
    const uint32_t bswz = ((uint32_t)(sq ^ (rB & 7))) << 4;

    float fb[FUSED ? 8 : 16];

    auto ldgB1 = [&](int p, int c) {                       // FUSED only; p literal
        const float* W   = (p < 2) ? W0 : W1;
        const int   wrow = p * 64 - ((p < 2) ? 0 : 128) + rB;
        const float* s = W + ((size_t)expert * I_DIM + nBase + wrow) * H_DIM
                           + sq * 8 + c * BKE;
        float4 v0 = reinterpret_cast<const float4*>(s)[0];
        float4 v1 = reinterpret_cast<const float4*>(s)[1];
        fb[0] = v0.x; fb[1] = v0.y; fb[2] = v0.z; fb[3] = v0.w;
        fb[4] = v1.x; fb[5] = v1.y; fb[6] = v1.z; fb[7] = v1.w;
    };
    auto stsB1 = [&](int p, uint32_t stg) {                // FUSED only; p literal
        uint32_t wh[4], wl[4];
#pragma unroll
        for (int q = 0; q < 4; ++q)
            split2(fb[q * 2], fb[q * 2 + 1], wh[q], wl[q]);
        uint32_t d = (uint32_t)(p * 64 + rB) * 128u + bswz;
        STS128(stg + OFF_BH + d, wh[0], wh[1], wh[2], wh[3]);
        STS128(stg + OFF_BL + d, wl[0], wl[1], wl[2], wl[3]);
    };

    // ---- DOWN B fill: 128 rows, 4 thr/row, 16 floats/thread (fb[16]) ----
    const int dbrow = tid >> 2;                            // 0..127
    const int dbk   = (tid & 3) * 16;
    const float* dbsrc = FUSED ? nullptr
        : (W0 + ((size_t)expert * H_DIM + nBase + dbrow) * I_DIM + dbk);
    const uint32_t dbswz_base = (uint32_t)dbrow * 128u;
    const uint32_t dbrsw = (uint32_t)(dbrow & 7);
    const uint32_t dbs0  = (uint32_t)(dbk >> 3);

    auto ldgB2 = [&](int c) {
        const float* s = dbsrc + c * BKE;
#pragma unroll
        for (int i = 0; i < 4; ++i) {
            float4 v = reinterpret_cast<const float4*>(s)[i];
            fb[i * 4 + 0] = v.x; fb[i * 4 + 1] = v.y;
            fb[i * 4 + 2] = v.z; fb[i * 4 + 3] = v.w;
        }
    };
    auto stsB2 = [&](uint32_t stg) {
#pragma unroll
        for (int q = 0; q < 2; ++q) {
            uint32_t wh[4], wl[4];
#pragma unroll
            for (int p = 0; p < 4; ++p)
                split2(fb[q * 8 + p * 2], fb[q * 8 + p * 2 + 1], wh[p], wl[p]);
            uint32_t d = dbswz_base + (((dbs0 + q) ^ dbrsw) << 4);
            STS128(stg + OFF_BH + d, wh[0], wh[1], wh[2], wh[3]);
            STS128(stg + OFF_BL + d, wl[0], wl[1], wl[2], wl[3]);
        }
    };

    // ---- ldmatrix lane geometry (warp tile 32x32, 4M x 4N) ----
    const int wm = wid >> 2;                               // 0..3 : M * 32
    const int wn = wid & 3;                                // 0..3 : N * 32
    const uint32_t lrow = (uint32_t)(lid & 15);
    const uint32_t lseg = (uint32_t)(lid >> 4);
    const uint32_t lxor = lrow & 7;

    float acc_g[2][4][4];                                  // [mt][n8][4]
    float acc_u[FUSED ? 2 : 1][FUSED ? 4 : 1][4];
#pragma unroll
    for (int a = 0; a < 2; ++a)
#pragma unroll
        for (int b = 0; b < 4; ++b)
#pragma unroll
            for (int c = 0; c < 4; ++c) acc_g[a][b][c] = 0.f;
#pragma unroll
    for (int a = 0; a < (FUSED ? 2 : 1); ++a)
#pragma unroll
        for (int b = 0; b < (FUSED ? 4 : 1); ++b)
#pragma unroll
            for (int c = 0; c < 4; ++c) acc_u[a][b][c] = 0.f;

    // one ks quarter of compute (ks literal at call sites)
    auto compute_ks = [&](uint32_t cur, int ks) {
        const uint32_t segx = (((uint32_t)(ks * 2) + lseg) ^ lxor) << 4;

        uint32_t aH[2][4], aL[2][4];
#pragma unroll
        for (int mt = 0; mt < 2; ++mt) {
            uint32_t off = ((uint32_t)(wm * 32 + mt * 16) + lrow) * 128u + segx;
            LDSM4(aH[mt], cur + 0u     + off);
            LDSM4(aL[mt], cur + OFF_AL + off);
        }

        uint32_t bh[2][4], bl[2][4];
#pragma unroll
        for (int grp = 0; grp < 2; ++grp) {                // gate | down rows
            uint32_t off = ((uint32_t)(wn * 32 + grp * 16) + lrow) * 128u + segx;
            LDSM4(bh[grp], cur + OFF_BH + off);
            LDSM4(bl[grp], cur + OFF_BL + off);
        }
#pragma unroll
        for (int mt = 0; mt < 2; ++mt)
#pragma unroll
            for (int grp = 0; grp < 2; ++grp)
#pragma unroll
                for (int half = 0; half < 2; ++half) {
                    MMA_BF16(acc_g[mt][grp * 2 + half], aH[mt],
                             bh[grp][half], bh[grp][half + 2]);        // hh
                    MMA_BF16(acc_g[mt][grp * 2 + half], aH[mt],
                             bl[grp][half], bl[grp][half + 2]);        // hl
                    MMA_BF16(acc_g[mt][grp * 2 + half], aL[mt],
                             bh[grp][half], bh[grp][half + 2]);        // lh
                }

        if (FUSED) {                                       // up rows 128..255
#pragma unroll
            for (int grp = 0; grp < 2; ++grp) {
                uint32_t off = ((uint32_t)(128 + wn * 32 + grp * 16) + lrow) * 128u + segx;
                LDSM4(bh[grp], cur + OFF_BH + off);
                LDSM4(bl[grp], cur + OFF_BL + off);
            }
#pragma unroll
            for (int mt = 0; mt < 2; ++mt)
#pragma unroll
                for (int grp = 0; grp < 2; ++grp)
#pragma unroll
                    for (int half = 0; half < 2; ++half) {
                        MMA_BF16(acc_u[mt][grp * 2 + half], aH[mt],
                                 bh[grp][half], bh[grp][half + 2]);
                        MMA_BF16(acc_u[mt][grp * 2 + half], aH[mt],
                                 bl[grp][half], bl[grp][half + 2]);
                        MMA_BF16(acc_u[mt][grp * 2 + half], aL[mt],
                                 bh[grp][half], bh[grp][half + 2]);
                    }
        }
    };

    // ---- prologue: fill buffer 0 ----
    if (FUSED) {
        cpA(0, sb);
        ldgB1(0, 0); stsB1(0, sb);
        ldgB1(1, 0); stsB1(1, sb);
        ldgB1(2, 0); stsB1(2, sb);
        ldgB1(3, 0); stsB1(3, sb);
    } else {
        cpA(0, sb);
        ldgB2(0); stsB2(sb);
    }
    CP_ASYNC_WAIT0();
    __syncthreads();

    // ---- main loop: 2-stage double buffer, B fill interleaved by ks ----
    for (int c = 0; c < KT; ++c) {
        const uint32_t cur = sb + (uint32_t)(c & 1) * STAGE;
        const uint32_t nxt = sb + (uint32_t)((c + 1) & 1) * STAGE;
        const bool more = (c + 1 < KT);
        if (more) cpA(c + 1, nxt);

        if (FUSED) {
            if (more) ldgB1(0, c + 1);
            compute_ks(cur, 0);
            if (more) { stsB1(0, nxt); ldgB1(1, c + 1); }
            compute_ks(cur, 1);
            if (more) { stsB1(1, nxt); ldgB1(2, c + 1); }
            compute_ks(cur, 2);
            if (more) { stsB1(2, nxt); ldgB1(3, c + 1); }
            compute_ks(cur, 3);
            if (more) stsB1(3, nxt);
        } else {
            if (more) ldgB2(c + 1);
            compute_ks(cur, 0);
            compute_ks(cur, 1);
            compute_ks(cur, 2);
            compute_ks(cur, 3);
            if (more) stsB2(nxt);
        }

        if (more) {
            CP_ASYNC_WAIT0();             // A(c+1) landed
            __syncthreads();              // cur fully read; nxt visible
        }
    }

    // ---- epilogue ----
    const int rbase = mBase + wm * 32 + (lid >> 2);
    const int cbase = nBase + wn * 32 + (lid & 3) * 2;

    if (FUSED) {
#pragma unroll
        for (int mt = 0; mt < 2; ++mt)
#pragma unroll
            for (int nt = 0; nt < 4; ++nt)
#pragma unroll
                for (int hr = 0; hr < 2; ++hr) {
                    int row = rbase + mt * 16 + hr * 8;
                    int col = cbase + nt * 8;
                    float h0 = silu_f(acc_g[mt][nt][hr * 2 + 0]) *
                               acc_u[mt][nt][hr * 2 + 0];
                    float h1 = silu_f(acc_g[mt][nt][hr * 2 + 1]) *
                               acc_u[mt][nt][hr * 2 + 1];
                    bf16 h0h, h0l, h1h, h1l;
                    split_bf(h0, h0h, h0l);
                    split_bf(h1, h1h, h1l);
                    size_t o = (size_t)row * I_DIM + col;
                    *reinterpret_cast<uint32_t*>(g_Hh + o) = pk2(h0h, h1h);
                    *reinterpret_cast<uint32_t*>(g_Hl + o) = pk2(h0l, h1l);
                }
    } else {
#pragma unroll
        for (int mt = 0; mt < 2; ++mt)
#pragma unroll
            for (int hr = 0; hr < 2; ++hr) {
                int row = rbase + mt * 16 + hr * 8;
                int token = g_perm[row];
                if (token >= 0) {
#pragma unroll
                    for (int nt = 0; nt < 4; ++nt) {
                        int col = cbase + nt * 8;
                        *reinterpret_cast<float2*>(out + (size_t)token * H_DIM + col) =
                            make_float2(acc_g[mt][nt][hr * 2 + 0],
                                        acc_g[mt][nt][hr * 2 + 1]);
                    }
                }
            }
    }
}

// ---------------------------------------------------------------------------
// Launch (graph-capturable: kernel launches only)
// ---------------------------------------------------------------------------
extern "C" void kernel_launch(void* const* d_in, const int* in_sizes, int n_in,
                              void* d_out, int out_size) {
    (void)in_sizes; (void)n_in; (void)out_size;
    const float* x   = (const float*)d_in[0];
    const int*   idx = (const int*)d_in[1];
    const float* Wg  = (const float*)d_in[2];
    const float* Wu  = (const float*)d_in[3];
    const float* Wd  = (const float*)d_in[4];
    float* out = (float*)d_out;

    constexpr int SMEM1 = 2 * 98304;     // 192 KB (FUSED)
    constexpr int SMEM2 = 2 * 65536;     // 128 KB (DOWN)
    cudaFuncSetAttribute(k_gemm_mma<true>,
                         cudaFuncAttributeMaxDynamicSharedMemorySize, SMEM1);
    cudaFuncSetAttribute(k_gemm_mma<false>,
                         cudaFuncAttributeMaxDynamicSharedMemorySize, SMEM2);

    k_init   <<<(PADDED + 255) / 256, 256>>>();
    k_count  <<<T_TOK / 256, 256>>>(idx);
    k_scan   <<<1, 32>>>();
    k_scatter<<<T_TOK / 256, 256>>>(idx);
    k_gather_cvt<<<PADDED, 256>>>(x);

    // mt fastest (blockIdx.x) -> concurrent CTAs share weight tiles in L2
    dim3 g1(MAX_TILES, I_DIM / BN);               // 72 x 22
    k_gemm_mma<true><<<g1, 512, SMEM1>>>(Wg, Wu, nullptr);

    dim3 g2(MAX_TILES, H_DIM / BN);               // 72 x 8
    k_gemm_mma<false><<<g2, 512, SMEM2>>>(Wd, nullptr, out);
}

// round 13
// speedup vs baseline: 2.8122x; 1.3840x over previous
#include <cuda_runtime.h>
#include <cuda_fp16.h>
#include <cstdint>
#include <cstddef>

typedef __half h16;

// Problem constants (T,H,I,E = 8192,1024,2816,8)
#define T_TOK 8192
#define H_DIM 1024
#define I_DIM 2816
#define N_EXP 8
#define BM 128
#define BN 128
#define BKE 64                              // K elems per chunk
#define MAX_TILES ((T_TOK / BM) + N_EXP)    // 72
#define PADDED    (MAX_TILES * BM)          // 9216

// ---------------------------------------------------------------------------
// Device scratch: 141.6 MB total — the footprint that passes the memory guard.
// (fp16 replaces bf16; element sizes identical)
// ---------------------------------------------------------------------------
__device__ int g_counts[N_EXP];
__device__ int g_wpos[N_EXP];
__device__ int g_tile_expert[MAX_TILES];
__device__ int g_perm[PADDED];
__device__ h16 g_Xh[(size_t)PADDED * H_DIM];   // 18.9 MB
__device__ h16 g_Xl[(size_t)PADDED * H_DIM];   // 18.9 MB
__device__ h16 g_Hh[(size_t)PADDED * I_DIM];   // 51.9 MB
__device__ h16 g_Hl[(size_t)PADDED * I_DIM];   // 51.9 MB

// ---------------------------------------------------------------------------
// PTX helpers — all non-arch-conditional (compute_100-legal).
// ---------------------------------------------------------------------------
__device__ __forceinline__ uint32_t smem_u32(const void* p) {
    uint32_t a;
    asm("{ .reg .u64 t; cvta.to.shared.u64 t, %1; cvt.u32.u64 %0, t; }"
        : "=r"(a) : "l"(p));
    return a;
}
__device__ __forceinline__ void cp_async16(uint32_t dst, const void* src) {
    asm volatile("cp.async.cg.shared.global [%0], [%1], 16;"
                 :: "r"(dst), "l"(src) : "memory");
}
#define CP_ASYNC_COMMIT() asm volatile("cp.async.commit_group;" ::: "memory")
#define CP_ASYNC_WAIT0()  asm volatile("cp.async.wait_group 0;" ::: "memory")

#define LDSM4(r, addr) \
    asm volatile("ldmatrix.sync.aligned.m8n8.x4.shared.b16 {%0,%1,%2,%3}, [%4];" \
        : "=r"((r)[0]), "=r"((r)[1]), "=r"((r)[2]), "=r"((r)[3]) : "r"(addr))

#define STS128(addr, w0, w1, w2, w3) \
    asm volatile("st.shared.v4.b32 [%0], {%1,%2,%3,%4};" \
        :: "r"(addr), "r"(w0), "r"(w1), "r"(w2), "r"(w3) : "memory")

// D(16x8,f32) += A(16x16,f16 row) * B(16x8,f16 col); d compile-time indexed.
#define MMA_F16(d, a, b0_, b1_) \
    asm volatile("mma.sync.aligned.m16n8k16.row.col.f32.f16.f16.f32 " \
        "{%0,%1,%2,%3}, {%4,%5,%6,%7}, {%8,%9}, {%0,%1,%2,%3};" \
        : "+f"((d)[0]), "+f"((d)[1]), "+f"((d)[2]), "+f"((d)[3]) \
        : "r"((a)[0]), "r"((a)[1]), "r"((a)[2]), "r"((a)[3]), "r"(b0_), "r"(b1_))

// pack two fp32 -> f16x2 word (f0 -> bits[15:0], f1 -> bits[31:16])
__device__ __forceinline__ uint32_t cvt2h(float f0, float f1) {
    __half2 t = __floats2half2_rn(f0, f1);
    return *reinterpret_cast<uint32_t*>(&t);
}
// hi/lo fp16 split of a float pair: wh = packed hi, wl = packed residuals
__device__ __forceinline__ void split2h(float f0, float f1,
                                        uint32_t& wh, uint32_t& wl) {
    wh = cvt2h(f0, f1);
    __half2 hv = *reinterpret_cast<__half2*>(&wh);
    wl = cvt2h(f0 - __half2float(__low2half(hv)),
               f1 - __half2float(__high2half(hv)));
}
// single fp16 rounding of a float pair (B path — one limb only)
__device__ __forceinline__ uint32_t round2h(float f0, float f1) {
    return cvt2h(f0, f1);
}
__device__ __forceinline__ float silu_f(float v) { return v / (1.0f + __expf(-v)); }

// ---------------------------------------------------------------------------
// Permutation build
// ---------------------------------------------------------------------------
__global__ void k_init() {
    int i = blockIdx.x * blockDim.x + threadIdx.x;
    if (i < PADDED) g_perm[i] = -1;
    if (i < N_EXP)  g_counts[i] = 0;
}
__global__ void k_count(const int* __restrict__ idx) {
    int t = blockIdx.x * blockDim.x + threadIdx.x;
    if (t < T_TOK) atomicAdd(&g_counts[idx[t]], 1);
}
__global__ void k_scan() {
    if (threadIdx.x == 0 && blockIdx.x == 0) {
        int base = 0, tile = 0;
        for (int e = 0; e < N_EXP; ++e) {
            g_wpos[e] = base;
            int nt = (g_counts[e] + BM - 1) / BM;
            for (int i = 0; i < nt; ++i) g_tile_expert[tile++] = e;
            base += nt * BM;
        }
        for (; tile < MAX_TILES; ++tile) g_tile_expert[tile] = -1;   // dead tiles
    }
}
__global__ void k_scatter(const int* __restrict__ idx) {
    int t = blockIdx.x * blockDim.x + threadIdx.x;
    if (t < T_TOK) {
        int p = atomicAdd(&g_wpos[idx[t]], 1);
        g_perm[p] = t;
    }
}
// Gather tokens (grouped order) and split fp32 -> fp16 hi/lo. Padding -> zeros.
__global__ void k_gather_cvt(const float* __restrict__ x) {
    int row = blockIdx.x;
    int t = g_perm[row];
    int j = threadIdx.x;                 // 256 threads, one float4 each (H=1024)
    float4 v = make_float4(0.f, 0.f, 0.f, 0.f);
    if (t >= 0) v = reinterpret_cast<const float4*>(x + (size_t)t * H_DIM)[j];
    uint32_t h0, l0, h1, l1;
    split2h(v.x, v.y, h0, l0);
    split2h(v.z, v.w, h1, l1);
    size_t o = (size_t)row * H_DIM + j * 4;
    *reinterpret_cast<uint2*>(g_Xh + o) = make_uint2(h0, h1);
    *reinterpret_cast<uint2*>(g_Xl + o) = make_uint2(l0, l1);
}

// ---------------------------------------------------------------------------
// Grouped GEMM on legacy tensor cores (mma.sync m16n8k16 f16, fp32 accum).
// fp16 2-pass split:  C = Ah*B + Al*B
//   A carries 22 effective mantissa bits (hi+lo fp16); B is a SINGLE fp16
//   limb (11 bits, rounding error ~2.8e-4 statistical — 1e-3 gate has 2x
//   margin). vs the bf16 3-pass scheme this cuts MMA count by 33% (the
//   binding resource per R9/R11 post-mortems) and halves B-side SMEM.
//
// BN=128, warp tile 32x32 (4M x 4N, 16 warps), 2-stage double buffer,
// SMEM rows 128B with XOR-16B swizzle, ldmatrix.x4.
// Stage layout: A_H 0, A_L 16K, B 32K.
//   FUSED: B 256 rows = 32K, stage 64K x2 = 128K.
//   DOWN : B 128 rows = 16K, stage 48K x2 =  96K.
// ---------------------------------------------------------------------------
template <bool FUSED>
__global__ __launch_bounds__(512, 1)
void k_gemm_mma(const float* __restrict__ W0,   // Wg | Wd
                const float* __restrict__ W1,   // Wu | (unused)
                float* __restrict__ out) {
    extern __shared__ char smem[];
    const uint32_t sb = smem_u32(smem);

    constexpr int KTOT = FUSED ? H_DIM : I_DIM;
    constexpr int KT   = KTOT / BKE;                       // 16 | 44
    constexpr int BROWS = FUSED ? 256 : 128;               // B tile rows
    constexpr uint32_t OFF_AL = 16384u;
    constexpr uint32_t OFF_B  = 32768u;
    constexpr uint32_t BTILE  = (uint32_t)BROWS * 128u;    // 32K | 16K
    constexpr uint32_t STAGE  = OFF_B + BTILE;             // 64K | 48K

    const int tid = threadIdx.x;
    const int wid = tid >> 5;
    const int lid = tid & 31;

    const int mt_blk = blockIdx.x;                         // mt fastest: weight
    const int expert = g_tile_expert[mt_blk];              // tiles shared in L2
    if (expert < 0) return;                                // dead tile
    const int mBase = mt_blk * BM;
    const int nBase = blockIdx.y * BN;

    const h16* __restrict__ Ah = FUSED ? g_Xh : g_Hh;
    const h16* __restrict__ Al = FUSED ? g_Xl : g_Hl;

    // ---- A fill geometry (cp.async fp16): 2 row-groups of 64 per thread ----
    const int r0  = tid >> 3;                              // 0..63
    const int seg = tid & 7;                               // 0..7
    const uint32_t swf = ((uint32_t)(seg ^ (r0 & 7))) << 4;

    auto cpA = [&](int c, uint32_t stg) {
        const int k0 = c * BKE;
#pragma unroll
        for (int i = 0; i < 2; ++i) {
            int r = r0 + 64 * i;
            size_t ao = (size_t)(mBase + r) * KTOT + k0 + seg * 8;
            uint32_t d = (uint32_t)r * 128u + swf;
            cp_async16(stg + 0u     + d, Ah + ao);
            cp_async16(stg + OFF_AL + d, Al + ao);
        }
        CP_ASYNC_COMMIT();
    };

    // ---- FUSED B fill: 4 passes, 64 rows x 8 floats/thread (fb[8]) ----
    // pass p covers rows [p*64, p*64+64): p<2 -> gate (W0), p>=2 -> up (W1).
    const int rB   = tid >> 3;                             // 0..63 row-in-pass
    const int sq   = tid & 7;                              // 16B seg 0..7
    const uint32_t bswz = ((uint32_t)(sq ^ (rB & 7))) << 4;

    float fb[FUSED ? 8 : 16];

    auto ldgB1 = [&](int p, int c) {                       // FUSED only; p literal
        const float* W   = (p < 2) ? W0 : W1;
        const int   wrow = p * 64 - ((p < 2) ? 0 : 128) + rB;
        const float* s = W + ((size_t)expert * I_DIM + nBase + wrow) * H_DIM
                           + sq * 8 + c * BKE;
        float4 v0 = reinterpret_cast<const float4*>(s)[0];
        float4 v1 = reinterpret_cast<const float4*>(s)[1];
        fb[0] = v0.x; fb[1] = v0.y; fb[2] = v0.z; fb[3] = v0.w;
        fb[4] = v1.x; fb[5] = v1.y; fb[6] = v1.z; fb[7] = v1.w;
    };
    auto stsB1 = [&](int p, uint32_t stg) {                // FUSED only; p literal
        uint32_t w[4];
#pragma unroll
        for (int q = 0; q < 4; ++q)
            w[q] = round2h(fb[q * 2], fb[q * 2 + 1]);
        uint32_t d = (uint32_t)(p * 64 + rB) * 128u + bswz;
        STS128(stg + OFF_B + d, w[0], w[1], w[2], w[3]);
    };

    // ---- DOWN B fill: 128 rows, 4 thr/row, 16 floats/thread (fb[16]) ----
    const int dbrow = tid >> 2;                            // 0..127
    const int dbk   = (tid & 3) * 16;
    const float* dbsrc = FUSED ? nullptr
        : (W0 + ((size_t)expert * H_DIM + nBase + dbrow) * I_DIM + dbk);
    const uint32_t dbswz_base = (uint32_t)dbrow * 128u;
    const uint32_t dbrsw = (uint32_t)(dbrow & 7);
    const uint32_t dbs0  = (uint32_t)(dbk >> 3);

    auto ldgB2 = [&](int c) {
        const float* s = dbsrc + c * BKE;
#pragma unroll
        for (int i = 0; i < 4; ++i) {
            float4 v = reinterpret_cast<const float4*>(s)[i];
            fb[i * 4 + 0] = v.x; fb[i * 4 + 1] = v.y;
            fb[i * 4 + 2] = v.z; fb[i * 4 + 3] = v.w;
        }
    };
    auto stsB2 = [&](uint32_t stg) {
#pragma unroll
        for (int q = 0; q < 2; ++q) {
            uint32_t w[4];
#pragma unroll
            for (int p = 0; p < 4; ++p)
                w[p] = round2h(fb[q * 8 + p * 2], fb[q * 8 + p * 2 + 1]);
            uint32_t d = dbswz_base + (((dbs0 + q) ^ dbrsw) << 4);
            STS128(stg + OFF_B + d, w[0], w[1], w[2], w[3]);
        }
    };

    // ---- ldmatrix lane geometry (warp tile 32x32, 4M x 4N) ----
    const int wm = wid >> 2;                               // 0..3 : M * 32
    const int wn = wid & 3;                                // 0..3 : N * 32
    const uint32_t lrow = (uint32_t)(lid & 15);
    const uint32_t lseg = (uint32_t)(lid >> 4);
    const uint32_t lxor = lrow & 7;

    float acc_g[2][4][4];                                  // [mt][n8][4]
    float acc_u[FUSED ? 2 : 1][FUSED ? 4 : 1][4];
#pragma unroll
    for (int a = 0; a < 2; ++a)
#pragma unroll
        for (int b = 0; b < 4; ++b)
#pragma unroll
            for (int c = 0; c < 4; ++c) acc_g[a][b][c] = 0.f;
#pragma unroll
    for (int a = 0; a < (FUSED ? 2 : 1); ++a)
#pragma unroll
        for (int b = 0; b < (FUSED ? 4 : 1); ++b)
#pragma unroll
            for (int c = 0; c < 4; ++c) acc_u[a][b][c] = 0.f;

    // one ks quarter of compute (ks literal at call sites)
    auto compute_ks = [&](uint32_t cur, int ks) {
        const uint32_t segx = (((uint32_t)(ks * 2) + lseg) ^ lxor) << 4;

        uint32_t aH[2][4], aL[2][4];
#pragma unroll
        for (int mt = 0; mt < 2; ++mt) {
            uint32_t off = ((uint32_t)(wm * 32 + mt * 16) + lrow) * 128u + segx;
            LDSM4(aH[mt], cur + 0u     + off);
            LDSM4(aL[mt], cur + OFF_AL + off);
        }

        uint32_t bb[2][4];
#pragma unroll
        for (int grp = 0; grp < 2; ++grp) {                // gate | down rows
            uint32_t off = ((uint32_t)(wn * 32 + grp * 16) + lrow) * 128u + segx;
            LDSM4(bb[grp], cur + OFF_B + off);
        }
#pragma unroll
        for (int mt = 0; mt < 2; ++mt)
#pragma unroll
            for (int grp = 0; grp < 2; ++grp)
#pragma unroll
                for (int half = 0; half < 2; ++half) {
                    MMA_F16(acc_g[mt][grp * 2 + half], aH[mt],
                            bb[grp][half], bb[grp][half + 2]);         // hi*B
                    MMA_F16(acc_g[mt][grp * 2 + half], aL[mt],
                            bb[grp][half], bb[grp][half + 2]);         // lo*B
                }

        if (FUSED) {                                       // up rows 128..255
#pragma unroll
            for (int grp = 0; grp < 2; ++grp) {
                uint32_t off = ((uint32_t)(128 + wn * 32 + grp * 16) + lrow) * 128u + segx;
                LDSM4(bb[grp], cur + OFF_B + off);
            }
#pragma unroll
            for (int mt = 0; mt < 2; ++mt)
#pragma unroll
                for (int grp = 0; grp < 2; ++grp)
#pragma unroll
                    for (int half = 0; half < 2; ++half) {
                        MMA_F16(acc_u[mt][grp * 2 + half], aH[mt],
                                bb[grp][half], bb[grp][half + 2]);
                        MMA_F16(acc_u[mt][grp * 2 + half], aL[mt],
                                bb[grp][half], bb[grp][half + 2]);
                    }
        }
    };

    // ---- prologue: fill buffer 0 ----
    if (FUSED) {
        cpA(0, sb);
        ldgB1(0, 0); stsB1(0, sb);
        ldgB1(1, 0); stsB1(1, sb);
        ldgB1(2, 0); stsB1(2, sb);
        ldgB1(3, 0); stsB1(3, sb);
    } else {
        cpA(0, sb);
        ldgB2(0); stsB2(sb);
    }
    CP_ASYNC_WAIT0();
    __syncthreads();

    // ---- main loop: 2-stage double buffer, B fill interleaved by ks ----
    for (int c = 0; c < KT; ++c) {
        const uint32_t cur = sb + (uint32_t)(c & 1) * STAGE;
        const uint32_t nxt = sb + (uint32_t)((c + 1) & 1) * STAGE;
        const bool more = (c + 1 < KT);
        if (more) cpA(c + 1, nxt);

        if (FUSED) {
            if (more) ldgB1(0, c + 1);
            compute_ks(cur, 0);
            if (more) { stsB1(0, nxt); ldgB1(1, c + 1); }
            compute_ks(cur, 1);
            if (more) { stsB1(1, nxt); ldgB1(2, c + 1); }
            compute_ks(cur, 2);
            if (more) { stsB1(2, nxt); ldgB1(3, c + 1); }
            compute_ks(cur, 3);
            if (more) stsB1(3, nxt);
        } else {
            if (more) ldgB2(c + 1);
            compute_ks(cur, 0);
            compute_ks(cur, 1);
            compute_ks(cur, 2);
            compute_ks(cur, 3);
            if (more) stsB2(nxt);
        }

        if (more) {
            CP_ASYNC_WAIT0();             // A(c+1) landed
            __syncthreads();              // cur fully read; nxt visible
        }
    }

    // ---- epilogue ----
    const int rbase = mBase + wm * 32 + (lid >> 2);
    const int cbase = nBase + wn * 32 + (lid & 3) * 2;

    if (FUSED) {
#pragma unroll
        for (int mt = 0; mt < 2; ++mt)
#pragma unroll
            for (int nt = 0; nt < 4; ++nt)
#pragma unroll
                for (int hr = 0; hr < 2; ++hr) {
                    int row = rbase + mt * 16 + hr * 8;
                    int col = cbase + nt * 8;
                    float h0 = silu_f(acc_g[mt][nt][hr * 2 + 0]) *
                               acc_u[mt][nt][hr * 2 + 0];
                    float h1 = silu_f(acc_g[mt][nt][hr * 2 + 1]) *
                               acc_u[mt][nt][hr * 2 + 1];
                    uint32_t wh, wl;
                    split2h(h0, h1, wh, wl);
                    size_t o = (size_t)row * I_DIM + col;
                    *reinterpret_cast<uint32_t*>(g_Hh + o) = wh;
                    *reinterpret_cast<uint32_t*>(g_Hl + o) = wl;
                }
    } else {
#pragma unroll
        for (int mt = 0; mt < 2; ++mt)
#pragma unroll
            for (int hr = 0; hr < 2; ++hr) {
                int row = rbase + mt * 16 + hr * 8;
                int token = g_perm[row];
                if (token >= 0) {
#pragma unroll
                    for (int nt = 0; nt < 4; ++nt) {
                        int col = cbase + nt * 8;
                        *reinterpret_cast<float2*>(out + (size_t)token * H_DIM + col) =
                            make_float2(acc_g[mt][nt][hr * 2 + 0],
                                        acc_g[mt][nt][hr * 2 + 1]);
                    }
                }
            }
    }
}

// ---------------------------------------------------------------------------
// Launch (graph-capturable: kernel launches only)
// ---------------------------------------------------------------------------
extern "C" void kernel_launch(void* const* d_in, const int* in_sizes, int n_in,
                              void* d_out, int out_size) {
    (void)in_sizes; (void)n_in; (void)out_size;
    const float* x   = (const float*)d_in[0];
    const int*   idx = (const int*)d_in[1];
    const float* Wg  = (const float*)d_in[2];
    const float* Wu  = (const float*)d_in[3];
    const float* Wd  = (const float*)d_in[4];
    float* out = (float*)d_out;

    constexpr int SMEM1 = 2 * 65536;     // 128 KB (FUSED)
    constexpr int SMEM2 = 2 * 49152;     //  96 KB (DOWN)
    cudaFuncSetAttribute(k_gemm_mma<true>,
                         cudaFuncAttributeMaxDynamicSharedMemorySize, SMEM1);
    cudaFuncSetAttribute(k_gemm_mma<false>,
                         cudaFuncAttributeMaxDynamicSharedMemorySize, SMEM2);

    k_init   <<<(PADDED + 255) / 256, 256>>>();
    k_count  <<<T_TOK / 256, 256>>>(idx);
    k_scan   <<<1, 32>>>();
    k_scatter<<<T_TOK / 256, 256>>>(idx);
    k_gather_cvt<<<PADDED, 256>>>(x);

    // mt fastest (blockIdx.x) -> concurrent CTAs share weight tiles in L2
    dim3 g1(MAX_TILES, I_DIM / BN);               // 72 x 22
    k_gemm_mma<true><<<g1, 512, SMEM1>>>(Wg, Wu, nullptr);

    dim3 g2(MAX_TILES, H_DIM / BN);               // 72 x 8
    k_gemm_mma<false><<<g2, 512, SMEM2>>>(Wd, nullptr, out);
}

// round 14
// speedup vs baseline: 3.8454x; 1.3674x over previous
#include <cuda_runtime.h>
#include <cuda_fp16.h>
#include <cstdint>
#include <cstddef>

typedef __half h16;

// Problem constants (T,H,I,E = 8192,1024,2816,8)
#define T_TOK 8192
#define H_DIM 1024
#define I_DIM 2816
#define N_EXP 8
#define BM 128
#define BN 128
#define BKE 64                              // K elems per chunk
#define MAX_TILES ((T_TOK / BM) + N_EXP)    // 72
#define PADDED    (MAX_TILES * BM)          // 9216

// ---------------------------------------------------------------------------
// Device scratch: 70.8 MB total (single fp16 limb; half of the footprint
// that already passed the memory guard).
// ---------------------------------------------------------------------------
__device__ int g_counts[N_EXP];
__device__ int g_wpos[N_EXP];
__device__ int g_tile_expert[MAX_TILES];
__device__ int g_perm[PADDED];
__device__ h16 g_X[(size_t)PADDED * H_DIM];   // 18.9 MB
__device__ h16 g_H[(size_t)PADDED * I_DIM];   // 51.9 MB

// ---------------------------------------------------------------------------
// PTX helpers — all non-arch-conditional (compute_100-legal).
// ---------------------------------------------------------------------------
__device__ __forceinline__ uint32_t smem_u32(const void* p) {
    uint32_t a;
    asm("{ .reg .u64 t; cvta.to.shared.u64 t, %1; cvt.u32.u64 %0, t; }"
        : "=r"(a) : "l"(p));
    return a;
}
__device__ __forceinline__ void cp_async16(uint32_t dst, const void* src) {
    asm volatile("cp.async.cg.shared.global [%0], [%1], 16;"
                 :: "r"(dst), "l"(src) : "memory");
}
#define CP_ASYNC_COMMIT() asm volatile("cp.async.commit_group;" ::: "memory")
#define CP_ASYNC_WAIT0()  asm volatile("cp.async.wait_group 0;" ::: "memory")

#define LDSM4(r, addr) \
    asm volatile("ldmatrix.sync.aligned.m8n8.x4.shared.b16 {%0,%1,%2,%3}, [%4];" \
        : "=r"((r)[0]), "=r"((r)[1]), "=r"((r)[2]), "=r"((r)[3]) : "r"(addr))

#define STS128(addr, w0, w1, w2, w3) \
    asm volatile("st.shared.v4.b32 [%0], {%1,%2,%3,%4};" \
        :: "r"(addr), "r"(w0), "r"(w1), "r"(w2), "r"(w3) : "memory")

// D(16x8,f32) += A(16x16,f16 row) * B(16x8,f16 col); d compile-time indexed.
#define MMA_F16(d, a, b0_, b1_) \
    asm volatile("mma.sync.aligned.m16n8k16.row.col.f32.f16.f16.f32 " \
        "{%0,%1,%2,%3}, {%4,%5,%6,%7}, {%8,%9}, {%0,%1,%2,%3};" \
        : "+f"((d)[0]), "+f"((d)[1]), "+f"((d)[2]), "+f"((d)[3]) \
        : "r"((a)[0]), "r"((a)[1]), "r"((a)[2]), "r"((a)[3]), "r"(b0_), "r"(b1_))

// pack two fp32 -> f16x2 word (f0 -> bits[15:0], f1 -> bits[31:16])
__device__ __forceinline__ uint32_t cvt2h(float f0, float f1) {
    __half2 t = __floats2half2_rn(f0, f1);
    return *reinterpret_cast<uint32_t*>(&t);
}
__device__ __forceinline__ float silu_f(float v) { return v / (1.0f + __expf(-v)); }

// ---------------------------------------------------------------------------
// Permutation build
// ---------------------------------------------------------------------------
__global__ void k_init() {
    int i = blockIdx.x * blockDim.x + threadIdx.x;
    if (i < PADDED) g_perm[i] = -1;
    if (i < N_EXP)  g_counts[i] = 0;
}
__global__ void k_count(const int* __restrict__ idx) {
    int t = blockIdx.x * blockDim.x + threadIdx.x;
    if (t < T_TOK) atomicAdd(&g_counts[idx[t]], 1);
}
__global__ void k_scan() {
    if (threadIdx.x == 0 && blockIdx.x == 0) {
        int base = 0, tile = 0;
        for (int e = 0; e < N_EXP; ++e) {
            g_wpos[e] = base;
            int nt = (g_counts[e] + BM - 1) / BM;
            for (int i = 0; i < nt; ++i) g_tile_expert[tile++] = e;
            base += nt * BM;
        }
        for (; tile < MAX_TILES; ++tile) g_tile_expert[tile] = -1;   // dead tiles
    }
}
__global__ void k_scatter(const int* __restrict__ idx) {
    int t = blockIdx.x * blockDim.x + threadIdx.x;
    if (t < T_TOK) {
        int p = atomicAdd(&g_wpos[idx[t]], 1);
        g_perm[p] = t;
    }
}
// Gather tokens (grouped order), round fp32 -> fp16. Padding -> zeros.
__global__ void k_gather_cvt(const float* __restrict__ x) {
    int row = blockIdx.x;
    int t = g_perm[row];
    int j = threadIdx.x;                 // 256 threads, one float4 each (H=1024)
    float4 v = make_float4(0.f, 0.f, 0.f, 0.f);
    if (t >= 0) v = reinterpret_cast<const float4*>(x + (size_t)t * H_DIM)[j];
    size_t o = (size_t)row * H_DIM + j * 4;
    *reinterpret_cast<uint2*>(g_X + o) =
        make_uint2(cvt2h(v.x, v.y), cvt2h(v.z, v.w));
}

// ---------------------------------------------------------------------------
// Grouped GEMM on legacy tensor cores: PLAIN fp16 mma.sync m16n8k16, fp32
// accumulate. One MMA pass per logical tile (half of R12's 2-pass scheme —
// MMA count was the binding resource per R11/R12 post-mortems).
//
// Numerics: A (x ~ N(0,1) / hid ~ O(1)) and B (W ~ N(0, 1/sqrt(K))) each
// carry fp16's 11-bit mantissa; calibrated error model predicts ~4.5e-4
// aggregate vs the 1e-3 gate (R12 measured 3.64e-4 with B-only rounding).
//
// BN=128, warp tile 32x32 (4M x 4N, 16 warps), 2-stage double buffer,
// SMEM rows 128B with XOR-16B swizzle, ldmatrix.x4.
// Stage layout: A 0 (16K), B 16K.
//   FUSED: B 256 rows = 32K, stage 48K x2 = 96K.
//   DOWN : B 128 rows = 16K, stage 32K x2 = 64K.
// ---------------------------------------------------------------------------
template <bool FUSED>
__global__ __launch_bounds__(512, 1)
void k_gemm_mma(const float* __restrict__ W0,   // Wg | Wd
                const float* __restrict__ W1,   // Wu | (unused)
                float* __restrict__ out) {
    extern __shared__ char smem[];
    const uint32_t sb = smem_u32(smem);

    constexpr int KTOT = FUSED ? H_DIM : I_DIM;
    constexpr int KT   = KTOT / BKE;                       // 16 | 44
    constexpr int BROWS = FUSED ? 256 : 128;               // B tile rows
    constexpr uint32_t OFF_B  = 16384u;
    constexpr uint32_t BTILE  = (uint32_t)BROWS * 128u;    // 32K | 16K
    constexpr uint32_t STAGE  = OFF_B + BTILE;             // 48K | 32K

    const int tid = threadIdx.x;
    const int wid = tid >> 5;
    const int lid = tid & 31;

    const int mt_blk = blockIdx.x;                         // mt fastest: weight
    const int expert = g_tile_expert[mt_blk];              // tiles shared in L2
    if (expert < 0) return;                                // dead tile
    const int mBase = mt_blk * BM;
    const int nBase = blockIdx.y * BN;

    const h16* __restrict__ A = FUSED ? g_X : g_H;

    // ---- A fill geometry (cp.async fp16): 2 row-groups of 64 per thread ----
    const int r0  = tid >> 3;                              // 0..63
    const int seg = tid & 7;                               // 0..7
    const uint32_t swf = ((uint32_t)(seg ^ (r0 & 7))) << 4;

    auto cpA = [&](int c, uint32_t stg) {
        const int k0 = c * BKE;
#pragma unroll
        for (int i = 0; i < 2; ++i) {
            int r = r0 + 64 * i;
            size_t ao = (size_t)(mBase + r) * KTOT + k0 + seg * 8;
            cp_async16(stg + (uint32_t)r * 128u + swf, A + ao);
        }
        CP_ASYNC_COMMIT();
    };

    // ---- FUSED B fill: 4 passes, 64 rows x 8 floats/thread (fb[8]) ----
    // pass p covers rows [p*64, p*64+64): p<2 -> gate (W0), p>=2 -> up (W1).
    const int rB   = tid >> 3;                             // 0..63 row-in-pass
    const int sq   = tid & 7;                              // 16B seg 0..7
    const uint32_t bswz = ((uint32_t)(sq ^ (rB & 7))) << 4;

    float fb[FUSED ? 8 : 16];

    auto ldgB1 = [&](int p, int c) {                       // FUSED only; p literal
        const float* W   = (p < 2) ? W0 : W1;
        const int   wrow = p * 64 - ((p < 2) ? 0 : 128) + rB;
        const float* s = W + ((size_t)expert * I_DIM + nBase + wrow) * H_DIM
                           + sq * 8 + c * BKE;
        float4 v0 = reinterpret_cast<const float4*>(s)[0];
        float4 v1 = reinterpret_cast<const float4*>(s)[1];
        fb[0] = v0.x; fb[1] = v0.y; fb[2] = v0.z; fb[3] = v0.w;
        fb[4] = v1.x; fb[5] = v1.y; fb[6] = v1.z; fb[7] = v1.w;
    };
    auto stsB1 = [&](int p, uint32_t stg) {                // FUSED only; p literal
        uint32_t w[4];
#pragma unroll
        for (int q = 0; q < 4; ++q)
            w[q] = cvt2h(fb[q * 2], fb[q * 2 + 1]);
        uint32_t d = (uint32_t)(p * 64 + rB) * 128u + bswz;
        STS128(stg + OFF_B + d, w[0], w[1], w[2], w[3]);
    };

    // ---- DOWN B fill: 128 rows, 4 thr/row, 16 floats/thread (fb[16]) ----
    const int dbrow = tid >> 2;                            // 0..127
    const int dbk   = (tid & 3) * 16;
    const float* dbsrc = FUSED ? nullptr
        : (W0 + ((size_t)expert * H_DIM + nBase + dbrow) * I_DIM + dbk);
    const uint32_t dbswz_base = (uint32_t)dbrow * 128u;
    const uint32_t dbrsw = (uint32_t)(dbrow & 7);
    const uint32_t dbs0  = (uint32_t)(dbk >> 3);

    auto ldgB2 = [&](int c) {
        const float* s = dbsrc + c * BKE;
#pragma unroll
        for (int i = 0; i < 4; ++i) {
            float4 v = reinterpret_cast<const float4*>(s)[i];
            fb[i * 4 + 0] = v.x; fb[i * 4 + 1] = v.y;
            fb[i * 4 + 2] = v.z; fb[i * 4 + 3] = v.w;
        }
    };
    auto stsB2 = [&](uint32_t stg) {
#pragma unroll
        for (int q = 0; q < 2; ++q) {
            uint32_t w[4];
#pragma unroll
            for (int p = 0; p < 4; ++p)
                w[p] = cvt2h(fb[q * 8 + p * 2], fb[q * 8 + p * 2 + 1]);
            uint32_t d = dbswz_base + (((dbs0 + q) ^ dbrsw) << 4);
            STS128(stg + OFF_B + d, w[0], w[1], w[2], w[3]);
        }
    };

    // ---- ldmatrix lane geometry (warp tile 32x32, 4M x 4N) ----
    const int wm = wid >> 2;                               // 0..3 : M * 32
    const int wn = wid & 3;                                // 0..3 : N * 32
    const uint32_t lrow = (uint32_t)(lid & 15);
    const uint32_t lseg = (uint32_t)(lid >> 4);
    const uint32_t lxor = lrow & 7;

    float acc_g[2][4][4];                                  // [mt][n8][4]
    float acc_u[FUSED ? 2 : 1][FUSED ? 4 : 1][4];
#pragma unroll
    for (int a = 0; a < 2; ++a)
#pragma unroll
        for (int b = 0; b < 4; ++b)
#pragma unroll
            for (int c = 0; c < 4; ++c) acc_g[a][b][c] = 0.f;
#pragma unroll
    for (int a = 0; a < (FUSED ? 2 : 1); ++a)
#pragma unroll
        for (int b = 0; b < (FUSED ? 4 : 1); ++b)
#pragma unroll
            for (int c = 0; c < 4; ++c) acc_u[a][b][c] = 0.f;

    // one ks quarter of compute (ks literal at call sites)
    auto compute_ks = [&](uint32_t cur, int ks) {
        const uint32_t segx = (((uint32_t)(ks * 2) + lseg) ^ lxor) << 4;

        uint32_t aF[2][4];
#pragma unroll
        for (int mt = 0; mt < 2; ++mt) {
            uint32_t off = ((uint32_t)(wm * 32 + mt * 16) + lrow) * 128u + segx;
            LDSM4(aF[mt], cur + off);
        }

        uint32_t bb[2][4];
#pragma unroll
        for (int grp = 0; grp < 2; ++grp) {                // gate | down rows
            uint32_t off = ((uint32_t)(wn * 32 + grp * 16) + lrow) * 128u + segx;
            LDSM4(bb[grp], cur + OFF_B + off);
        }
#pragma unroll
        for (int mt = 0; mt < 2; ++mt)
#pragma unroll
            for (int grp = 0; grp < 2; ++grp)
#pragma unroll
                for (int half = 0; half < 2; ++half)
                    MMA_F16(acc_g[mt][grp * 2 + half], aF[mt],
                            bb[grp][half], bb[grp][half + 2]);

        if (FUSED) {                                       // up rows 128..255
#pragma unroll
            for (int grp = 0; grp < 2; ++grp) {
                uint32_t off = ((uint32_t)(128 + wn * 32 + grp * 16) + lrow) * 128u + segx;
                LDSM4(bb[grp], cur + OFF_B + off);
            }
#pragma unroll
            for (int mt = 0; mt < 2; ++mt)
#pragma unroll
                for (int grp = 0; grp < 2; ++grp)
#pragma unroll
                    for (int half = 0; half < 2; ++half)
                        MMA_F16(acc_u[mt][grp * 2 + half], aF[mt],
                                bb[grp][half], bb[grp][half + 2]);
        }
    };

    // ---- prologue: fill buffer 0 ----
    if (FUSED) {
        cpA(0, sb);
        ldgB1(0, 0); stsB1(0, sb);
        ldgB1(1, 0); stsB1(1, sb);
        ldgB1(2, 0); stsB1(2, sb);
        ldgB1(3, 0); stsB1(3, sb);
    } else {
        cpA(0, sb);
        ldgB2(0); stsB2(sb);
    }
    CP_ASYNC_WAIT0();
    __syncthreads();

    // ---- main loop: 2-stage double buffer, B fill interleaved by ks ----
    for (int c = 0; c < KT; ++c) {
        const uint32_t cur = sb + (uint32_t)(c & 1) * STAGE;
        const uint32_t nxt = sb + (uint32_t)((c + 1) & 1) * STAGE;
        const bool more = (c + 1 < KT);
        if (more) cpA(c + 1, nxt);

        if (FUSED) {
            if (more) ldgB1(0, c + 1);
            compute_ks(cur, 0);
            if (more) { stsB1(0, nxt); ldgB1(1, c + 1); }
            compute_ks(cur, 1);
            if (more) { stsB1(1, nxt); ldgB1(2, c + 1); }
            compute_ks(cur, 2);
            if (more) { stsB1(2, nxt); ldgB1(3, c + 1); }
            compute_ks(cur, 3);
            if (more) stsB1(3, nxt);
        } else {
            if (more) ldgB2(c + 1);
            compute_ks(cur, 0);
            compute_ks(cur, 1);
            compute_ks(cur, 2);
            compute_ks(cur, 3);
            if (more) stsB2(nxt);
        }

        if (more) {
            CP_ASYNC_WAIT0();             // A(c+1) landed
            __syncthreads();              // cur fully read; nxt visible
        }
    }

    // ---- epilogue ----
    const int rbase = mBase + wm * 32 + (lid >> 2);
    const int cbase = nBase + wn * 32 + (lid & 3) * 2;

    if (FUSED) {
#pragma unroll
        for (int mt = 0; mt < 2; ++mt)
#pragma unroll
            for (int nt = 0; nt < 4; ++nt)
#pragma unroll
                for (int hr = 0; hr < 2; ++hr) {
                    int row = rbase + mt * 16 + hr * 8;
                    int col = cbase + nt * 8;
                    float h0 = silu_f(acc_g[mt][nt][hr * 2 + 0]) *
                               acc_u[mt][nt][hr * 2 + 0];
                    float h1 = silu_f(acc_g[mt][nt][hr * 2 + 1]) *
                               acc_u[mt][nt][hr * 2 + 1];
                    *reinterpret_cast<uint32_t*>(
                        g_H + (size_t)row * I_DIM + col) = cvt2h(h0, h1);
                }
    } else {
#pragma unroll
        for (int mt = 0; mt < 2; ++mt)
#pragma unroll
            for (int hr = 0; hr < 2; ++hr) {
                int row = rbase + mt * 16 + hr * 8;
                int token = g_perm[row];
                if (token >= 0) {
#pragma unroll
                    for (int nt = 0; nt < 4; ++nt) {
                        int col = cbase + nt * 8;
                        *reinterpret_cast<float2*>(out + (size_t)token * H_DIM + col) =
                            make_float2(acc_g[mt][nt][hr * 2 + 0],
                                        acc_g[mt][nt][hr * 2 + 1]);
                    }
                }
            }
    }
}

// ---------------------------------------------------------------------------
// Launch (graph-capturable: kernel launches only)
// ---------------------------------------------------------------------------
extern "C" void kernel_launch(void* const* d_in, const int* in_sizes, int n_in,
                              void* d_out, int out_size) {
    (void)in_sizes; (void)n_in; (void)out_size;
    const float* x   = (const float*)d_in[0];
    const int*   idx = (const int*)d_in[1];
    const float* Wg  = (const float*)d_in[2];
    const float* Wu  = (const float*)d_in[3];
    const float* Wd  = (const float*)d_in[4];
    float* out = (float*)d_out;

    constexpr int SMEM1 = 2 * 49152;     // 96 KB (FUSED)
    constexpr int SMEM2 = 2 * 32768;     // 64 KB (DOWN)
    cudaFuncSetAttribute(k_gemm_mma<true>,
                         cudaFuncAttributeMaxDynamicSharedMemorySize, SMEM1);
    cudaFuncSetAttribute(k_gemm_mma<false>,
                         cudaFuncAttributeMaxDynamicSharedMemorySize, SMEM2);

    k_init   <<<(PADDED + 255) / 256, 256>>>();
    k_count  <<<T_TOK / 256, 256>>>(idx);
    k_scan   <<<1, 32>>>();
    k_scatter<<<T_TOK / 256, 256>>>(idx);
    k_gather_cvt<<<PADDED, 256>>>(x);

    // mt fastest (blockIdx.x) -> concurrent CTAs share weight tiles in L2
    dim3 g1(MAX_TILES, I_DIM / BN);               // 72 x 22
    k_gemm_mma<true><<<g1, 512, SMEM1>>>(Wg, Wu, nullptr);

    dim3 g2(MAX_TILES, H_DIM / BN);               // 72 x 8
    k_gemm_mma<false><<<g2, 512, SMEM2>>>(Wd, nullptr, out);
}